// round 2
// baseline (speedup 1.0000x reference)
#include <cuda_runtime.h>
#include <math.h>

// Problem constants (fixed shapes from reference)
#define BB    8
#define LL    4096
#define HH    512
#define PP    512
#define MM    (BB*LL)     // 32768 tokens
#define N1    (2*PP)      // 1024  (Bu_re | Bu_im)
#define K1    HH          // 512
#define N2    HH          // 512
#define K2    (2*PP)      // 1024  (x_re | x_im)
#define NCHUNK 32
#define CLEN   128        // LL / NCHUNK

// ---------------- static device scratch (no runtime allocation) -------------
__device__ float  d_W1[N1 * K1];                 // [n=2P][k=H]  B_bar folded
__device__ float  d_W2[N2 * K2];                 // [h][k=2P]    [2C_re | -2C_im]
__device__ float  d_X [(size_t)MM * N1];         // Bu, scanned in-place -> xs (128MB)
__device__ float2 d_Lam[PP];                     // Lambda_bar
__device__ float2 d_LamPow[PP];                  // Lambda_bar^CLEN
__device__ float2 d_yend[BB * NCHUNK * PP];      // per-chunk local end state
__device__ float2 d_cin [BB * NCHUNK * PP];      // per-chunk carry-in

// ---------------- setup: discretize in fp64, build W1 -----------------------
__global__ void setup_kernel(const float* __restrict__ Lre, const float* __restrict__ Lim,
                             const float* __restrict__ Bre, const float* __restrict__ Bim,
                             const float* __restrict__ log_step) {
    int p = blockIdx.x;
    __shared__ float2 s_f;
    if (threadIdx.x == 0) {
        double lr = (double)Lre[p], li = (double)Lim[p];
        double dt = exp((double)log_step[p]);
        double mag = exp(lr * dt);
        double lam_r = mag * cos(li * dt);
        double lam_i = mag * sin(li * dt);
        d_Lam[p] = make_float2((float)lam_r, (float)lam_i);
        // f = (lam - 1) / (lr + i*li)
        double nr = lam_r - 1.0, ni = lam_i;
        double den = lr * lr + li * li;
        s_f = make_float2((float)((nr * lr + ni * li) / den),
                          (float)((ni * lr - nr * li) / den));
        // lam^128 via 7 squarings (double)
        double pr = lam_r, pi = lam_i;
        #pragma unroll
        for (int i = 0; i < 7; i++) {
            double r2 = pr * pr - pi * pi;
            double i2 = 2.0 * pr * pi;
            pr = r2; pi = i2;
        }
        d_LamPow[p] = make_float2((float)pr, (float)pi);
    }
    __syncthreads();
    float fr = s_f.x, fi = s_f.y;
    for (int h = threadIdx.x; h < HH; h += blockDim.x) {
        float br = Bre[p * HH + h];
        float bi = Bim[p * HH + h];
        d_W1[p * K1 + h]        = fr * br - fi * bi;   // Re(B_bar)
        d_W1[(PP + p) * K1 + h] = fr * bi + fi * br;   // Im(B_bar)
    }
}

__global__ void w2_kernel(const float* __restrict__ Cre, const float* __restrict__ Cim) {
    int idx = blockIdx.x * blockDim.x + threadIdx.x;   // over H*P
    int h = idx >> 9;          // /512
    int p = idx & (PP - 1);
    d_W2[h * K2 + p]      =  2.0f * Cre[h * PP + p];
    d_W2[h * K2 + PP + p] = -2.0f * Cim[h * PP + p];
}

// ---------------- fp32 tiled SGEMM: C[m,n] = sum_k A[m,k] * W[n,k] ----------
// A: M x K row-major, W: N x K row-major (both K-contiguous -> "TN" GEMM)
__global__ __launch_bounds__(256, 2)
void sgemm_tn(const float* __restrict__ A, const float* __restrict__ W,
              float* __restrict__ C, int M, int N, int K) {
    const int BM = 128, BN = 128, BK = 16;
    __shared__ __align__(16) float As[BK][BM];
    __shared__ __align__(16) float Ws[BK][BN];
    int m0 = blockIdx.y * BM;
    int n0 = blockIdx.x * BN;
    int tid = threadIdx.x;
    int tx = tid & 15;          // 0..15 -> n sub
    int ty = tid >> 4;          // 0..15 -> m sub

    float acc[8][8] = {};

    for (int kt = 0; kt < K; kt += BK) {
        #pragma unroll
        for (int i = 0; i < 2; i++) {
            int lin = tid + i * 256;        // 0..511
            int row = lin >> 2;             // 0..127
            int c4  = (lin & 3) << 2;       // 0,4,8,12
            float4 av = *(const float4*)(A + (size_t)(m0 + row) * K + kt + c4);
            As[c4 + 0][row] = av.x; As[c4 + 1][row] = av.y;
            As[c4 + 2][row] = av.z; As[c4 + 3][row] = av.w;
            float4 wv = *(const float4*)(W + (size_t)(n0 + row) * K + kt + c4);
            Ws[c4 + 0][row] = wv.x; Ws[c4 + 1][row] = wv.y;
            Ws[c4 + 2][row] = wv.z; Ws[c4 + 3][row] = wv.w;
        }
        __syncthreads();
        #pragma unroll
        for (int k = 0; k < BK; k++) {
            float a[8], w[8];
            #pragma unroll
            for (int i = 0; i < 8; i++) a[i] = As[k][ty * 8 + i];
            #pragma unroll
            for (int j = 0; j < 8; j++) w[j] = Ws[k][tx * 8 + j];
            #pragma unroll
            for (int i = 0; i < 8; i++)
                #pragma unroll
                for (int j = 0; j < 8; j++)
                    acc[i][j] += a[i] * w[j];
        }
        __syncthreads();
    }

    #pragma unroll
    for (int i = 0; i < 8; i++) {
        float4* cp = (float4*)(C + (size_t)(m0 + ty * 8 + i) * N + n0 + tx * 8);
        cp[0] = make_float4(acc[i][0], acc[i][1], acc[i][2], acc[i][3]);
        cp[1] = make_float4(acc[i][4], acc[i][5], acc[i][6], acc[i][7]);
    }
}

// ---------------- chunked complex scan over L (constant Lambda) -------------
// idx layout: [b][chunk][p], p fastest (coalesced across p)
__global__ void scan_phaseA() {
    int idx = blockIdx.x * blockDim.x + threadIdx.x;
    int p = idx & (PP - 1);
    int c = (idx >> 9) & (NCHUNK - 1);
    int b = idx >> 14;
    float2 lam = d_Lam[p];
    float xr = 0.f, xi = 0.f;
    size_t base = ((size_t)b * LL + (size_t)c * CLEN) * N1;
    const float* Xr = d_X + base + p;
    const float* Xi = d_X + base + PP + p;
    #pragma unroll 4
    for (int j = 0; j < CLEN; j++) {
        float br = Xr[(size_t)j * N1];
        float bi = Xi[(size_t)j * N1];
        float nr = fmaf(lam.x, xr, fmaf(-lam.y, xi, br));
        float ni = fmaf(lam.x, xi, fmaf( lam.y, xr, bi));
        xr = nr; xi = ni;
    }
    d_yend[(b * NCHUNK + c) * PP + p] = make_float2(xr, xi);
}

__global__ void scan_phaseB() {
    int idx = blockIdx.x * blockDim.x + threadIdx.x;   // b*P threads
    int p = idx & (PP - 1);
    int b = idx >> 9;
    float2 pw = d_LamPow[p];
    float cr = 0.f, ci = 0.f;
    #pragma unroll
    for (int c = 0; c < NCHUNK; c++) {
        d_cin[(b * NCHUNK + c) * PP + p] = make_float2(cr, ci);
        float2 ye = d_yend[(b * NCHUNK + c) * PP + p];
        float nr = fmaf(pw.x, cr, fmaf(-pw.y, ci, ye.x));
        float ni = fmaf(pw.x, ci, fmaf( pw.y, cr, ye.y));
        cr = nr; ci = ni;
    }
}

__global__ void scan_phaseC() {
    int idx = blockIdx.x * blockDim.x + threadIdx.x;
    int p = idx & (PP - 1);
    int c = (idx >> 9) & (NCHUNK - 1);
    int b = idx >> 14;
    float2 lam = d_Lam[p];
    float2 c0 = d_cin[(b * NCHUNK + c) * PP + p];
    float xr = c0.x, xi = c0.y;
    size_t base = ((size_t)b * LL + (size_t)c * CLEN) * N1;
    float* Xr = d_X + base + p;
    float* Xi = d_X + base + PP + p;
    #pragma unroll 4
    for (int j = 0; j < CLEN; j++) {
        float br = Xr[(size_t)j * N1];
        float bi = Xi[(size_t)j * N1];
        float nr = fmaf(lam.x, xr, fmaf(-lam.y, xi, br));
        float ni = fmaf(lam.x, xi, fmaf( lam.y, xr, bi));
        xr = nr; xi = ni;
        Xr[(size_t)j * N1] = xr;
        Xi[(size_t)j * N1] = xi;
    }
}

// ---------------- launch -----------------------------------------------------
extern "C" void kernel_launch(void* const* d_in, const int* in_sizes, int n_in,
                              void* d_out, int out_size) {
    const float* Lre      = (const float*)d_in[0];
    const float* Lim      = (const float*)d_in[1];
    const float* Bre      = (const float*)d_in[2];
    const float* Bim      = (const float*)d_in[3];
    const float* Cre      = (const float*)d_in[4];
    const float* Cim      = (const float*)d_in[5];
    const float* log_step = (const float*)d_in[6];
    const float* u        = (const float*)d_in[7];
    float* out = (float*)d_out;

    float *W1p, *W2p, *Xp;
    cudaGetSymbolAddress((void**)&W1p, d_W1);
    cudaGetSymbolAddress((void**)&W2p, d_W2);
    cudaGetSymbolAddress((void**)&Xp,  d_X);

    setup_kernel<<<PP, 256>>>(Lre, Lim, Bre, Bim, log_step);
    w2_kernel<<<(HH * PP) / 256, 256>>>(Cre, Cim);

    // GEMM1: Bu(re|im) = u @ W1^T   -> d_X  (M x 1024)
    sgemm_tn<<<dim3(N1 / 128, MM / 128), 256>>>(u, W1p, Xp, MM, N1, K1);

    // chunked complex scan over time, in-place in d_X
    scan_phaseA<<<(BB * NCHUNK * PP) / 256, 256>>>();
    scan_phaseB<<<(BB * PP) / 256, 256>>>();
    scan_phaseC<<<(BB * NCHUNK * PP) / 256, 256>>>();

    // GEMM2: ys = X @ W2^T  -> out (M x 512)
    sgemm_tn<<<dim3(N2 / 128, MM / 128), 256>>>(Xp, W2p, out, MM, N2, K2);
}

// round 4
// speedup vs baseline: 2.0683x; 2.0683x over previous
#include <cuda_runtime.h>
#include <cuda_bf16.h>
#include <math.h>
#include <stdint.h>

// Problem constants
#define BB    8
#define LL    4096
#define HH    512
#define PP    512
#define MM    (BB*LL)     // 32768 tokens
#define N1    (2*PP)      // 1024  (Bu_re | Bu_im)
#define K1    HH          // 512
#define N2    HH          // 512
#define K2    (2*PP)      // 1024  (x_re | x_im)
#define NCHUNK 32
#define CLEN   128        // LL / NCHUNK

// ---------------- static device scratch -------------------------------------
__device__ float          d_X  [(size_t)MM * N1];   // Bu fp32 (128MB)
__device__ __nv_bfloat16  d_Uhi[(size_t)MM * K1];
__device__ __nv_bfloat16  d_Ulo[(size_t)MM * K1];
__device__ __nv_bfloat16  d_Xhi[(size_t)MM * K2];
__device__ __nv_bfloat16  d_Xlo[(size_t)MM * K2];
__device__ __nv_bfloat16  d_W1hi[N1 * K1];
__device__ __nv_bfloat16  d_W1lo[N1 * K1];
__device__ __nv_bfloat16  d_W2hi[N2 * K2];
__device__ __nv_bfloat16  d_W2lo[N2 * K2];
__device__ float2 d_Lam[PP];
__device__ float2 d_LamPow[PP];
__device__ float2 d_yend[BB * NCHUNK * PP];
__device__ float2 d_cin [BB * NCHUNK * PP];

// ---------------- helpers ----------------------------------------------------
__device__ __forceinline__ uint32_t smem_u32(const void* p) {
    uint32_t a;
    asm("{ .reg .u64 t; cvta.to.shared.u64 t, %1; cvt.u32.u64 %0, t; }" : "=r"(a) : "l"(p));
    return a;
}
__device__ __forceinline__ void cp16(uint32_t saddr, const void* g) {
    asm volatile("cp.async.cg.shared.global [%0], [%1], 16;" :: "r"(saddr), "l"(g));
}
#define CP_COMMIT() asm volatile("cp.async.commit_group;" ::: "memory")
#define CP_WAIT1()  asm volatile("cp.async.wait_group 1;" ::: "memory")

__device__ __forceinline__ void ldm_x4(uint32_t addr, uint32_t* r) {
    asm volatile("ldmatrix.sync.aligned.m8n8.x4.shared.b16 {%0,%1,%2,%3}, [%4];"
                 : "=r"(r[0]), "=r"(r[1]), "=r"(r[2]), "=r"(r[3]) : "r"(addr));
}
__device__ __forceinline__ void hmma(float* c, const uint32_t* a, const uint32_t* b) {
    asm volatile(
        "mma.sync.aligned.m16n8k16.row.col.f32.bf16.bf16.f32 "
        "{%0,%1,%2,%3}, {%4,%5,%6,%7}, {%8,%9}, {%0,%1,%2,%3};"
        : "+f"(c[0]), "+f"(c[1]), "+f"(c[2]), "+f"(c[3])
        : "r"(a[0]), "r"(a[1]), "r"(a[2]), "r"(a[3]), "r"(b[0]), "r"(b[1]));
}
__device__ __forceinline__ void split_bf16(float x, __nv_bfloat16& h, __nv_bfloat16& l) {
    h = __float2bfloat16(x);
    l = __float2bfloat16(x - __bfloat162float(h));
}

// ---------------- setup: discretize in fp64, build split W1 -----------------
__global__ void setup_kernel(const float* __restrict__ Lre, const float* __restrict__ Lim,
                             const float* __restrict__ Bre, const float* __restrict__ Bim,
                             const float* __restrict__ log_step) {
    int p = blockIdx.x;
    __shared__ float2 s_f;
    if (threadIdx.x == 0) {
        double lr = (double)Lre[p], li = (double)Lim[p];
        double dt = exp((double)log_step[p]);
        double mag = exp(lr * dt);
        double lam_r = mag * cos(li * dt);
        double lam_i = mag * sin(li * dt);
        d_Lam[p] = make_float2((float)lam_r, (float)lam_i);
        double nr = lam_r - 1.0, ni = lam_i;
        double den = lr * lr + li * li;
        s_f = make_float2((float)((nr * lr + ni * li) / den),
                          (float)((ni * lr - nr * li) / den));
        double pr = lam_r, pi = lam_i;
        #pragma unroll
        for (int i = 0; i < 7; i++) { double r2 = pr*pr - pi*pi, i2 = 2.0*pr*pi; pr = r2; pi = i2; }
        d_LamPow[p] = make_float2((float)pr, (float)pi);
    }
    __syncthreads();
    float fr = s_f.x, fi = s_f.y;
    for (int h = threadIdx.x; h < HH; h += blockDim.x) {
        float br = Bre[p * HH + h], bi = Bim[p * HH + h];
        float wr = fr * br - fi * bi;
        float wi = fr * bi + fi * br;
        split_bf16(wr, d_W1hi[p * K1 + h],        d_W1lo[p * K1 + h]);
        split_bf16(wi, d_W1hi[(PP + p) * K1 + h], d_W1lo[(PP + p) * K1 + h]);
    }
}

__global__ void w2_kernel(const float* __restrict__ Cre, const float* __restrict__ Cim) {
    int idx = blockIdx.x * blockDim.x + threadIdx.x;
    int h = idx >> 9, p = idx & (PP - 1);
    split_bf16( 2.0f * Cre[h * PP + p], d_W2hi[h * K2 + p],      d_W2lo[h * K2 + p]);
    split_bf16(-2.0f * Cim[h * PP + p], d_W2hi[h * K2 + PP + p], d_W2lo[h * K2 + PP + p]);
}

__global__ void usplit_kernel(const float* __restrict__ u) {
    size_t i = (size_t)blockIdx.x * blockDim.x + threadIdx.x;
    float v = u[i];
    split_bf16(v, d_Uhi[i], d_Ulo[i]);
}

// ---------------- HMMA split-bf16 GEMM: C[m,n] = sum_k A[m,k]*W[n,k] --------
// 128x128 CTA tile, BK=32, 8 warps of 64x32, cp.async double buffer.
#define PAD_STRIDE 80                     // 32 bf16 = 64B data, padded to 80B
#define TILE_B  (128 * PAD_STRIDE)       // 10240 B
#define STAGE_B (4 * TILE_B)             // Ahi, Alo, Whi, Wlo
#define GSMEM   (2 * STAGE_B)            // 81920 B

__global__ void __launch_bounds__(256, 1)
hmma_gemm(const __nv_bfloat16* __restrict__ Ahi, const __nv_bfloat16* __restrict__ Alo,
          const __nv_bfloat16* __restrict__ Whi, const __nv_bfloat16* __restrict__ Wlo,
          float* __restrict__ C, int N, int K) {
    extern __shared__ char smem[];
    const uint32_t sb = smem_u32(smem);
    const int tid = threadIdx.x;
    const int wid = tid >> 5, lane = tid & 31;
    const int wm = wid >> 2, wn = wid & 3;       // warp tile: rows wm*64, cols wn*32
    const int m0 = blockIdx.y * 128, n0 = blockIdx.x * 128;

    const char* srcs[4] = {
        (const char*)(Ahi + (size_t)m0 * K), (const char*)(Alo + (size_t)m0 * K),
        (const char*)(Whi + (size_t)n0 * K), (const char*)(Wlo + (size_t)n0 * K) };
    const size_t rstride = (size_t)K * 2;

    const int gtile = tid >> 6;         // 0..3 -> which of the 4 tiles this thread loads
    const int lt    = tid & 63;

    auto prefetch = [&](int stage, int ci) {
        const char* src = srcs[gtile] + (size_t)ci * 64;      // 32 bf16 per k-chunk
        uint32_t tb = sb + stage * STAGE_B + gtile * TILE_B;
        #pragma unroll
        for (int i = 0; i < 8; i++) {
            int chunk = lt + i * 64;             // 0..511
            int row = chunk >> 2, c = chunk & 3;
            cp16(tb + row * PAD_STRIDE + c * 16, src + (size_t)row * rstride + c * 16);
        }
    };

    float acc[4][4][4];
    #pragma unroll
    for (int i = 0; i < 4; i++)
        #pragma unroll
        for (int j = 0; j < 4; j++)
            #pragma unroll
            for (int q = 0; q < 4; q++) acc[i][j][q] = 0.f;

    const int nch = K / 32;
    prefetch(0, 0); CP_COMMIT();
    prefetch(1, 1); CP_COMMIT();

    // fragment address components (per lane)
    const int a_row = lane & 15;
    const int a_kof = (lane >> 4) * 8;                       // 0 or 8
    const int b_row = (lane & 7) + ((lane >> 4) & 1) * 8;    // 0..15
    const int b_kof = ((lane >> 3) & 1) * 8;                 // 0 or 8

    for (int ci = 0; ci < nch; ci++) {
        int s = ci & 1;
        CP_WAIT1();
        __syncthreads();

        uint32_t sAhi = sb + s * STAGE_B + 0 * TILE_B;
        uint32_t sAlo = sb + s * STAGE_B + 1 * TILE_B;
        uint32_t sWhi = sb + s * STAGE_B + 2 * TILE_B;
        uint32_t sWlo = sb + s * STAGE_B + 3 * TILE_B;

        #pragma unroll
        for (int ks = 0; ks < 2; ks++) {
            const int k0 = ks * 16;
            uint32_t ahi[4][4], alo[4][4], bhi[4][2], blo[4][2];
            #pragma unroll
            for (int mt = 0; mt < 4; mt++) {
                uint32_t off = (uint32_t)((wm * 64 + mt * 16 + a_row) * PAD_STRIDE
                                          + (k0 + a_kof) * 2);
                ldm_x4(sAhi + off, ahi[mt]);
                ldm_x4(sAlo + off, alo[mt]);
            }
            #pragma unroll
            for (int np = 0; np < 2; np++) {
                uint32_t off = (uint32_t)((wn * 32 + np * 16 + b_row) * PAD_STRIDE
                                          + (k0 + b_kof) * 2);
                uint32_t r[4];
                ldm_x4(sWhi + off, r);
                bhi[np*2][0] = r[0]; bhi[np*2][1] = r[1];
                bhi[np*2+1][0] = r[2]; bhi[np*2+1][1] = r[3];
                ldm_x4(sWlo + off, r);
                blo[np*2][0] = r[0]; blo[np*2][1] = r[1];
                blo[np*2+1][0] = r[2]; blo[np*2+1][1] = r[3];
            }
            #pragma unroll
            for (int mt = 0; mt < 4; mt++)
                #pragma unroll
                for (int nt = 0; nt < 4; nt++) {
                    hmma(acc[mt][nt], ahi[mt], bhi[nt]);
                    hmma(acc[mt][nt], ahi[mt], blo[nt]);
                    hmma(acc[mt][nt], alo[mt], bhi[nt]);
                }
        }
        __syncthreads();
        if (ci + 2 < nch) prefetch(s, ci + 2);
        CP_COMMIT();
    }

    // epilogue: fragment layout c0,c1 -> (row lane/4, col (lane%4)*2), c2,c3 -> row+8
    #pragma unroll
    for (int mt = 0; mt < 4; mt++) {
        int r = m0 + wm * 64 + mt * 16 + (lane >> 2);
        #pragma unroll
        for (int nt = 0; nt < 4; nt++) {
            int c = n0 + wn * 32 + nt * 8 + (lane & 3) * 2;
            *(float2*)(C + (size_t)r * N + c)       = make_float2(acc[mt][nt][0], acc[mt][nt][1]);
            *(float2*)(C + (size_t)(r + 8) * N + c) = make_float2(acc[mt][nt][2], acc[mt][nt][3]);
        }
    }
}

// ---------------- chunked complex scan over L --------------------------------
__global__ void scan_phaseA() {
    int idx = blockIdx.x * blockDim.x + threadIdx.x;
    int p = idx & (PP - 1);
    int c = (idx >> 9) & (NCHUNK - 1);
    int b = idx >> 14;
    float2 lam = d_Lam[p];
    float xr = 0.f, xi = 0.f;
    size_t base = ((size_t)b * LL + (size_t)c * CLEN) * N1;
    const float* Xr = d_X + base + p;
    const float* Xi = d_X + base + PP + p;
    #pragma unroll 4
    for (int j = 0; j < CLEN; j++) {
        float br = Xr[(size_t)j * N1];
        float bi = Xi[(size_t)j * N1];
        float nr = fmaf(lam.x, xr, fmaf(-lam.y, xi, br));
        float ni = fmaf(lam.x, xi, fmaf( lam.y, xr, bi));
        xr = nr; xi = ni;
    }
    d_yend[(b * NCHUNK + c) * PP + p] = make_float2(xr, xi);
}

__global__ void scan_phaseB() {
    int idx = blockIdx.x * blockDim.x + threadIdx.x;
    int p = idx & (PP - 1);
    int b = idx >> 9;
    float2 pw = d_LamPow[p];
    float cr = 0.f, ci = 0.f;
    #pragma unroll
    for (int c = 0; c < NCHUNK; c++) {
        d_cin[(b * NCHUNK + c) * PP + p] = make_float2(cr, ci);
        float2 ye = d_yend[(b * NCHUNK + c) * PP + p];
        float nr = fmaf(pw.x, cr, fmaf(-pw.y, ci, ye.x));
        float ni = fmaf(pw.x, ci, fmaf( pw.y, cr, ye.y));
        cr = nr; ci = ni;
    }
}

__global__ void scan_phaseC() {
    int idx = blockIdx.x * blockDim.x + threadIdx.x;
    int p = idx & (PP - 1);
    int c = (idx >> 9) & (NCHUNK - 1);
    int b = idx >> 14;
    float2 lam = d_Lam[p];
    float2 c0 = d_cin[(b * NCHUNK + c) * PP + p];
    float xr = c0.x, xi = c0.y;
    size_t mrow = (size_t)b * LL + (size_t)c * CLEN;
    const float* Xr = d_X + mrow * N1 + p;
    const float* Xi = d_X + mrow * N1 + PP + p;
    __nv_bfloat16* Hr = d_Xhi + mrow * K2 + p;
    __nv_bfloat16* Hi = d_Xhi + mrow * K2 + PP + p;
    __nv_bfloat16* Lr = d_Xlo + mrow * K2 + p;
    __nv_bfloat16* Li = d_Xlo + mrow * K2 + PP + p;
    #pragma unroll 4
    for (int j = 0; j < CLEN; j++) {
        float br = Xr[(size_t)j * N1];
        float bi = Xi[(size_t)j * N1];
        float nr = fmaf(lam.x, xr, fmaf(-lam.y, xi, br));
        float ni = fmaf(lam.x, xi, fmaf( lam.y, xr, bi));
        xr = nr; xi = ni;
        __nv_bfloat16 h, l;
        split_bf16(xr, h, l); Hr[(size_t)j * K2] = h; Lr[(size_t)j * K2] = l;
        split_bf16(xi, h, l); Hi[(size_t)j * K2] = h; Li[(size_t)j * K2] = l;
    }
}

// ---------------- launch -----------------------------------------------------
extern "C" void kernel_launch(void* const* d_in, const int* in_sizes, int n_in,
                              void* d_out, int out_size) {
    const float* Lre      = (const float*)d_in[0];
    const float* Lim      = (const float*)d_in[1];
    const float* Bre      = (const float*)d_in[2];
    const float* Bim      = (const float*)d_in[3];
    const float* Cre      = (const float*)d_in[4];
    const float* Cim      = (const float*)d_in[5];
    const float* log_step = (const float*)d_in[6];
    const float* u        = (const float*)d_in[7];
    float* out = (float*)d_out;

    float *Xp;
    __nv_bfloat16 *Uhi, *Ulo, *Xhi, *Xlo, *W1h, *W1l, *W2h, *W2l;
    cudaGetSymbolAddress((void**)&Xp,  d_X);
    cudaGetSymbolAddress((void**)&Uhi, d_Uhi);
    cudaGetSymbolAddress((void**)&Ulo, d_Ulo);
    cudaGetSymbolAddress((void**)&Xhi, d_Xhi);
    cudaGetSymbolAddress((void**)&Xlo, d_Xlo);
    cudaGetSymbolAddress((void**)&W1h, d_W1hi);
    cudaGetSymbolAddress((void**)&W1l, d_W1lo);
    cudaGetSymbolAddress((void**)&W2h, d_W2hi);
    cudaGetSymbolAddress((void**)&W2l, d_W2lo);

    cudaFuncSetAttribute(hmma_gemm, cudaFuncAttributeMaxDynamicSharedMemorySize, GSMEM);

    setup_kernel<<<PP, 256>>>(Lre, Lim, Bre, Bim, log_step);
    w2_kernel<<<(HH * PP) / 256, 256>>>(Cre, Cim);
    usplit_kernel<<<(int)(((size_t)MM * K1) / 256), 256>>>(u);

    // GEMM1: Bu(re|im) = u @ W1^T -> d_X fp32 (M x 1024)
    hmma_gemm<<<dim3(N1 / 128, MM / 128), 256, GSMEM>>>(Uhi, Ulo, W1h, W1l, Xp, N1, K1);

    // chunked complex scan; phaseC emits split-bf16 xs
    scan_phaseA<<<(BB * NCHUNK * PP) / 256, 256>>>();
    scan_phaseB<<<(BB * PP) / 256, 256>>>();
    scan_phaseC<<<(BB * NCHUNK * PP) / 256, 256>>>();

    // GEMM2: ys = xs @ W2^T -> out (M x 512)
    hmma_gemm<<<dim3(N2 / 128, MM / 128), 256, GSMEM>>>(Xhi, Xlo, W2h, W2l, out, N2, K2);
}

// round 5
// speedup vs baseline: 2.2793x; 1.1020x over previous
#include <cuda_runtime.h>
#include <cuda_bf16.h>
#include <math.h>
#include <stdint.h>

// Problem constants
#define BB    8
#define LL    4096
#define HH    512
#define PP    512
#define MM    (BB*LL)     // 32768 tokens
#define N1    (2*PP)      // 1024  (Bu_re | Bu_im)
#define K1    HH          // 512
#define N2    HH          // 512
#define K2    (2*PP)      // 1024  (x_re | x_im)
#define NCHUNK 32
#define CLEN   128        // LL / NCHUNK

// ---------------- static device scratch -------------------------------------
__device__ float          d_X  [(size_t)MM * N1];   // Bu fp32 (128MB)
__device__ __nv_bfloat16  d_Uhi[(size_t)MM * K1];
__device__ __nv_bfloat16  d_Ulo[(size_t)MM * K1];
__device__ __nv_bfloat16  d_Xhi[(size_t)MM * K2];
__device__ __nv_bfloat16  d_Xlo[(size_t)MM * K2];
__device__ __nv_bfloat16  d_W1hi[N1 * K1];
__device__ __nv_bfloat16  d_W1lo[N1 * K1];
__device__ __nv_bfloat16  d_W2hi[N2 * K2];
__device__ __nv_bfloat16  d_W2lo[N2 * K2];
__device__ float2 d_Lam[PP];
__device__ float2 d_LamPow[PP];
__device__ float2 d_yend[BB * NCHUNK * PP];
__device__ float2 d_cin [BB * NCHUNK * PP];

// ---------------- helpers ----------------------------------------------------
__device__ __forceinline__ uint32_t smem_u32(const void* p) {
    uint32_t a;
    asm("{ .reg .u64 t; cvta.to.shared.u64 t, %1; cvt.u32.u64 %0, t; }" : "=r"(a) : "l"(p));
    return a;
}
__device__ __forceinline__ void cp16(uint32_t saddr, const void* g) {
    asm volatile("cp.async.cg.shared.global [%0], [%1], 16;" :: "r"(saddr), "l"(g));
}
#define CP_COMMIT() asm volatile("cp.async.commit_group;" ::: "memory")
#define CP_WAIT1()  asm volatile("cp.async.wait_group 1;" ::: "memory")

__device__ __forceinline__ void ldm_x4(uint32_t addr, uint32_t* r) {
    asm volatile("ldmatrix.sync.aligned.m8n8.x4.shared.b16 {%0,%1,%2,%3}, [%4];"
                 : "=r"(r[0]), "=r"(r[1]), "=r"(r[2]), "=r"(r[3]) : "r"(addr));
}
__device__ __forceinline__ void hmma(float* c, const uint32_t* a, const uint32_t* b) {
    asm volatile(
        "mma.sync.aligned.m16n8k16.row.col.f32.bf16.bf16.f32 "
        "{%0,%1,%2,%3}, {%4,%5,%6,%7}, {%8,%9}, {%0,%1,%2,%3};"
        : "+f"(c[0]), "+f"(c[1]), "+f"(c[2]), "+f"(c[3])
        : "r"(a[0]), "r"(a[1]), "r"(a[2]), "r"(a[3]), "r"(b[0]), "r"(b[1]));
}
__device__ __forceinline__ void split_bf16(float x, __nv_bfloat16& h, __nv_bfloat16& l) {
    h = __float2bfloat16(x);
    l = __float2bfloat16(x - __bfloat162float(h));
}

// ---------------- setup: discretize in fp64, build split W1 -----------------
__global__ void setup_kernel(const float* __restrict__ Lre, const float* __restrict__ Lim,
                             const float* __restrict__ Bre, const float* __restrict__ Bim,
                             const float* __restrict__ log_step) {
    int p = blockIdx.x;
    __shared__ float2 s_f;
    if (threadIdx.x == 0) {
        double lr = (double)Lre[p], li = (double)Lim[p];
        double dt = exp((double)log_step[p]);
        double mag = exp(lr * dt);
        double lam_r = mag * cos(li * dt);
        double lam_i = mag * sin(li * dt);
        d_Lam[p] = make_float2((float)lam_r, (float)lam_i);
        double nr = lam_r - 1.0, ni = lam_i;
        double den = lr * lr + li * li;
        s_f = make_float2((float)((nr * lr + ni * li) / den),
                          (float)((ni * lr - nr * li) / den));
        double pr = lam_r, pi = lam_i;
        #pragma unroll
        for (int i = 0; i < 7; i++) { double r2 = pr*pr - pi*pi, i2 = 2.0*pr*pi; pr = r2; pi = i2; }
        d_LamPow[p] = make_float2((float)pr, (float)pi);
    }
    __syncthreads();
    float fr = s_f.x, fi = s_f.y;
    for (int h = threadIdx.x; h < HH; h += blockDim.x) {
        float br = Bre[p * HH + h], bi = Bim[p * HH + h];
        float wr = fr * br - fi * bi;
        float wi = fr * bi + fi * br;
        split_bf16(wr, d_W1hi[p * K1 + h],        d_W1lo[p * K1 + h]);
        split_bf16(wi, d_W1hi[(PP + p) * K1 + h], d_W1lo[(PP + p) * K1 + h]);
    }
}

__global__ void w2_kernel(const float* __restrict__ Cre, const float* __restrict__ Cim) {
    int idx = blockIdx.x * blockDim.x + threadIdx.x;
    int h = idx >> 9, p = idx & (PP - 1);
    split_bf16( 2.0f * Cre[h * PP + p], d_W2hi[h * K2 + p],      d_W2lo[h * K2 + p]);
    split_bf16(-2.0f * Cim[h * PP + p], d_W2hi[h * K2 + PP + p], d_W2lo[h * K2 + PP + p]);
}

__global__ void usplit_kernel(const float* __restrict__ u) {
    size_t i = (size_t)blockIdx.x * blockDim.x + threadIdx.x;
    float v = u[i];
    split_bf16(v, d_Uhi[i], d_Ulo[i]);
}

// ---------------- HMMA split-bf16 GEMM: C[m,n] = sum_k A[m,k]*W[n,k] --------
// 128x128 CTA tile, BK=32, 8 warps of 64x32, cp.async double buffer.
// Register-lean inner loop so 2 CTAs co-reside per SM.
#define PAD_STRIDE 80                     // 32 bf16 = 64B data, padded to 80B
#define TILE_B  (128 * PAD_STRIDE)       // 10240 B
#define STAGE_B (4 * TILE_B)             // Ahi, Alo, Whi, Wlo
#define GSMEM   (2 * STAGE_B)            // 81920 B

__global__ void __launch_bounds__(256, 2)
hmma_gemm(const __nv_bfloat16* __restrict__ Ahi, const __nv_bfloat16* __restrict__ Alo,
          const __nv_bfloat16* __restrict__ Whi, const __nv_bfloat16* __restrict__ Wlo,
          float* __restrict__ C, int N, int K) {
    extern __shared__ char smem[];
    const uint32_t sb = smem_u32(smem);
    const int tid = threadIdx.x;
    const int wid = tid >> 5, lane = tid & 31;
    const int wm = wid >> 2, wn = wid & 3;       // warp tile: rows wm*64, cols wn*32
    const int m0 = blockIdx.y * 128, n0 = blockIdx.x * 128;

    const char* srcs[4] = {
        (const char*)(Ahi + (size_t)m0 * K), (const char*)(Alo + (size_t)m0 * K),
        (const char*)(Whi + (size_t)n0 * K), (const char*)(Wlo + (size_t)n0 * K) };
    const size_t rstride = (size_t)K * 2;

    const int gtile = tid >> 6;         // 0..3 -> which of the 4 tiles this thread loads
    const int lt    = tid & 63;

    auto prefetch = [&](int stage, int ci) {
        const char* src = srcs[gtile] + (size_t)ci * 64;      // 32 bf16 per k-chunk
        uint32_t tb = sb + stage * STAGE_B + gtile * TILE_B;
        #pragma unroll
        for (int i = 0; i < 8; i++) {
            int chunk = lt + i * 64;             // 0..511
            int row = chunk >> 2, c = chunk & 3;
            cp16(tb + row * PAD_STRIDE + c * 16, src + (size_t)row * rstride + c * 16);
        }
    };

    float acc[4][4][4];
    #pragma unroll
    for (int i = 0; i < 4; i++)
        #pragma unroll
        for (int j = 0; j < 4; j++)
            #pragma unroll
            for (int q = 0; q < 4; q++) acc[i][j][q] = 0.f;

    const int nch = K / 32;
    prefetch(0, 0); CP_COMMIT();
    prefetch(1, 1); CP_COMMIT();

    // fragment address components (per lane)
    const int a_row = lane & 15;
    const int a_kof = (lane >> 4) * 8;                       // 0 or 8
    const int b_row = (lane & 7) + ((lane >> 4) & 1) * 8;    // 0..15
    const int b_kof = ((lane >> 3) & 1) * 8;                 // 0 or 8

    for (int ci = 0; ci < nch; ci++) {
        int s = ci & 1;
        CP_WAIT1();
        __syncthreads();

        uint32_t sAhi = sb + s * STAGE_B + 0 * TILE_B;
        uint32_t sAlo = sb + s * STAGE_B + 1 * TILE_B;
        uint32_t sWhi = sb + s * STAGE_B + 2 * TILE_B;
        uint32_t sWlo = sb + s * STAGE_B + 3 * TILE_B;

        #pragma unroll
        for (int ks = 0; ks < 2; ks++) {
            const int k0 = ks * 16;
            // B fragments for this k-step (16 regs live)
            uint32_t bhi[4][2], blo[4][2];
            #pragma unroll
            for (int np = 0; np < 2; np++) {
                uint32_t off = (uint32_t)((wn * 32 + np * 16 + b_row) * PAD_STRIDE
                                          + (k0 + b_kof) * 2);
                uint32_t r[4];
                ldm_x4(sWhi + off, r);
                bhi[np*2][0] = r[0]; bhi[np*2][1] = r[1];
                bhi[np*2+1][0] = r[2]; bhi[np*2+1][1] = r[3];
                ldm_x4(sWlo + off, r);
                blo[np*2][0] = r[0]; blo[np*2][1] = r[1];
                blo[np*2+1][0] = r[2]; blo[np*2+1][1] = r[3];
            }
            // A fragments loaded per-mt (8 regs live), MMAs fired immediately
            #pragma unroll
            for (int mt = 0; mt < 4; mt++) {
                uint32_t off = (uint32_t)((wm * 64 + mt * 16 + a_row) * PAD_STRIDE
                                          + (k0 + a_kof) * 2);
                uint32_t ahi[4], alo[4];
                ldm_x4(sAhi + off, ahi);
                ldm_x4(sAlo + off, alo);
                #pragma unroll
                for (int nt = 0; nt < 4; nt++) {
                    hmma(acc[mt][nt], ahi, bhi[nt]);
                    hmma(acc[mt][nt], ahi, blo[nt]);
                    hmma(acc[mt][nt], alo, bhi[nt]);
                }
            }
        }
        __syncthreads();
        if (ci + 2 < nch) prefetch(s, ci + 2);
        CP_COMMIT();
    }

    // epilogue: fragment layout c0,c1 -> (row lane/4, col (lane%4)*2), c2,c3 -> row+8
    #pragma unroll
    for (int mt = 0; mt < 4; mt++) {
        int r = m0 + wm * 64 + mt * 16 + (lane >> 2);
        #pragma unroll
        for (int nt = 0; nt < 4; nt++) {
            int c = n0 + wn * 32 + nt * 8 + (lane & 3) * 2;
            *(float2*)(C + (size_t)r * N + c)       = make_float2(acc[mt][nt][0], acc[mt][nt][1]);
            *(float2*)(C + (size_t)(r + 8) * N + c) = make_float2(acc[mt][nt][2], acc[mt][nt][3]);
        }
    }
}

// ---------------- chunked complex scan over L --------------------------------
__global__ void scan_phaseA() {
    int idx = blockIdx.x * blockDim.x + threadIdx.x;
    int p = idx & (PP - 1);
    int c = (idx >> 9) & (NCHUNK - 1);
    int b = idx >> 14;
    float2 lam = d_Lam[p];
    float xr = 0.f, xi = 0.f;
    size_t base = ((size_t)b * LL + (size_t)c * CLEN) * N1;
    const float* Xr = d_X + base + p;
    const float* Xi = d_X + base + PP + p;
    #pragma unroll 4
    for (int j = 0; j < CLEN; j++) {
        float br = Xr[(size_t)j * N1];
        float bi = Xi[(size_t)j * N1];
        float nr = fmaf(lam.x, xr, fmaf(-lam.y, xi, br));
        float ni = fmaf(lam.x, xi, fmaf( lam.y, xr, bi));
        xr = nr; xi = ni;
    }
    d_yend[(b * NCHUNK + c) * PP + p] = make_float2(xr, xi);
}

__global__ void scan_phaseB() {
    int idx = blockIdx.x * blockDim.x + threadIdx.x;
    int p = idx & (PP - 1);
    int b = idx >> 9;
    float2 pw = d_LamPow[p];
    float cr = 0.f, ci = 0.f;
    #pragma unroll
    for (int c = 0; c < NCHUNK; c++) {
        d_cin[(b * NCHUNK + c) * PP + p] = make_float2(cr, ci);
        float2 ye = d_yend[(b * NCHUNK + c) * PP + p];
        float nr = fmaf(pw.x, cr, fmaf(-pw.y, ci, ye.x));
        float ni = fmaf(pw.x, ci, fmaf( pw.y, cr, ye.y));
        cr = nr; ci = ni;
    }
}

__global__ void scan_phaseC() {
    int idx = blockIdx.x * blockDim.x + threadIdx.x;
    int p = idx & (PP - 1);
    int c = (idx >> 9) & (NCHUNK - 1);
    int b = idx >> 14;
    float2 lam = d_Lam[p];
    float2 c0 = d_cin[(b * NCHUNK + c) * PP + p];
    float xr = c0.x, xi = c0.y;
    size_t mrow = (size_t)b * LL + (size_t)c * CLEN;
    const float* Xr = d_X + mrow * N1 + p;
    const float* Xi = d_X + mrow * N1 + PP + p;
    __nv_bfloat16* Hr = d_Xhi + mrow * K2 + p;
    __nv_bfloat16* Hi = d_Xhi + mrow * K2 + PP + p;
    __nv_bfloat16* Lr = d_Xlo + mrow * K2 + p;
    __nv_bfloat16* Li = d_Xlo + mrow * K2 + PP + p;
    #pragma unroll 4
    for (int j = 0; j < CLEN; j++) {
        float br = Xr[(size_t)j * N1];
        float bi = Xi[(size_t)j * N1];
        float nr = fmaf(lam.x, xr, fmaf(-lam.y, xi, br));
        float ni = fmaf(lam.x, xi, fmaf( lam.y, xr, bi));
        xr = nr; xi = ni;
        __nv_bfloat16 h, l;
        split_bf16(xr, h, l); Hr[(size_t)j * K2] = h; Lr[(size_t)j * K2] = l;
        split_bf16(xi, h, l); Hi[(size_t)j * K2] = h; Li[(size_t)j * K2] = l;
    }
}

// ---------------- launch -----------------------------------------------------
extern "C" void kernel_launch(void* const* d_in, const int* in_sizes, int n_in,
                              void* d_out, int out_size) {
    const float* Lre      = (const float*)d_in[0];
    const float* Lim      = (const float*)d_in[1];
    const float* Bre      = (const float*)d_in[2];
    const float* Bim      = (const float*)d_in[3];
    const float* Cre      = (const float*)d_in[4];
    const float* Cim      = (const float*)d_in[5];
    const float* log_step = (const float*)d_in[6];
    const float* u        = (const float*)d_in[7];
    float* out = (float*)d_out;

    float *Xp;
    __nv_bfloat16 *Uhi, *Ulo, *Xhi, *Xlo, *W1h, *W1l, *W2h, *W2l;
    cudaGetSymbolAddress((void**)&Xp,  d_X);
    cudaGetSymbolAddress((void**)&Uhi, d_Uhi);
    cudaGetSymbolAddress((void**)&Ulo, d_Ulo);
    cudaGetSymbolAddress((void**)&Xhi, d_Xhi);
    cudaGetSymbolAddress((void**)&Xlo, d_Xlo);
    cudaGetSymbolAddress((void**)&W1h, d_W1hi);
    cudaGetSymbolAddress((void**)&W1l, d_W1lo);
    cudaGetSymbolAddress((void**)&W2h, d_W2hi);
    cudaGetSymbolAddress((void**)&W2l, d_W2lo);

    cudaFuncSetAttribute(hmma_gemm, cudaFuncAttributeMaxDynamicSharedMemorySize, GSMEM);

    setup_kernel<<<PP, 256>>>(Lre, Lim, Bre, Bim, log_step);
    w2_kernel<<<(HH * PP) / 256, 256>>>(Cre, Cim);
    usplit_kernel<<<(int)(((size_t)MM * K1) / 256), 256>>>(u);

    // GEMM1: Bu(re|im) = u @ W1^T -> d_X fp32 (M x 1024)
    hmma_gemm<<<dim3(N1 / 128, MM / 128), 256, GSMEM>>>(Uhi, Ulo, W1h, W1l, Xp, N1, K1);

    // chunked complex scan; phaseC emits split-bf16 xs
    scan_phaseA<<<(BB * NCHUNK * PP) / 256, 256>>>();
    scan_phaseB<<<(BB * PP) / 256, 256>>>();
    scan_phaseC<<<(BB * NCHUNK * PP) / 256, 256>>>();

    // GEMM2: ys = xs @ W2^T -> out (M x 512)
    hmma_gemm<<<dim3(N2 / 128, MM / 128), 256, GSMEM>>>(Xhi, Xlo, W2h, W2l, out, N2, K2);
}

// round 6
// speedup vs baseline: 2.6784x; 1.1751x over previous
#include <cuda_runtime.h>
#include <cuda_bf16.h>
#include <math.h>
#include <stdint.h>

// Problem constants
#define BB    8
#define LL    4096
#define HH    512
#define PP    512
#define MM    (BB*LL)     // 32768 tokens
#define N1    (2*PP)      // 1024  (Bu_re | Bu_im)
#define K1    HH          // 512
#define N2    HH          // 512
#define K2    (2*PP)      // 1024  (x_re | x_im)
#define NCHUNK 32
#define CLEN   128        // LL / NCHUNK

// ---------------- static device scratch -------------------------------------
__device__ float          d_X  [(size_t)MM * N1];   // Bu fp32 (128MB)
__device__ __nv_bfloat16  d_Uhi[(size_t)MM * K1];
__device__ __nv_bfloat16  d_Ulo[(size_t)MM * K1];
__device__ __nv_bfloat16  d_Xhi[(size_t)MM * K2];
__device__ __nv_bfloat16  d_Xlo[(size_t)MM * K2];
__device__ __nv_bfloat16  d_W1hi[N1 * K1];
__device__ __nv_bfloat16  d_W1lo[N1 * K1];
__device__ __nv_bfloat16  d_W2hi[N2 * K2];
__device__ __nv_bfloat16  d_W2lo[N2 * K2];
__device__ float2 d_Lam[PP];
__device__ float2 d_LamPow[PP];
__device__ float2 d_yend[BB * NCHUNK * PP];
__device__ float2 d_cin [BB * NCHUNK * PP];

// ---------------- helpers ----------------------------------------------------
__device__ __forceinline__ uint32_t smem_u32(const void* p) {
    uint32_t a;
    asm("{ .reg .u64 t; cvta.to.shared.u64 t, %1; cvt.u32.u64 %0, t; }" : "=r"(a) : "l"(p));
    return a;
}
__device__ __forceinline__ void cp16(uint32_t saddr, const void* g) {
    asm volatile("cp.async.cg.shared.global [%0], [%1], 16;" :: "r"(saddr), "l"(g));
}
#define CP_COMMIT() asm volatile("cp.async.commit_group;" ::: "memory")
#define CP_WAIT(n)  asm volatile("cp.async.wait_group %0;" :: "n"(n) : "memory")

__device__ __forceinline__ void ldm_x4(uint32_t addr, uint32_t* r) {
    asm volatile("ldmatrix.sync.aligned.m8n8.x4.shared.b16 {%0,%1,%2,%3}, [%4];"
                 : "=r"(r[0]), "=r"(r[1]), "=r"(r[2]), "=r"(r[3]) : "r"(addr));
}
__device__ __forceinline__ void hmma(float* c, const uint32_t* a, const uint32_t* b) {
    asm volatile(
        "mma.sync.aligned.m16n8k16.row.col.f32.bf16.bf16.f32 "
        "{%0,%1,%2,%3}, {%4,%5,%6,%7}, {%8,%9}, {%0,%1,%2,%3};"
        : "+f"(c[0]), "+f"(c[1]), "+f"(c[2]), "+f"(c[3])
        : "r"(a[0]), "r"(a[1]), "r"(a[2]), "r"(a[3]), "r"(b[0]), "r"(b[1]));
}
__device__ __forceinline__ void split_bf16(float x, __nv_bfloat16& h, __nv_bfloat16& l) {
    h = __float2bfloat16(x);
    l = __float2bfloat16(x - __bfloat162float(h));
}

// XOR swizzle inside a 128-row x 64B tile: (row, c16) -> byte offset
__device__ __forceinline__ uint32_t sw_off(int row, int c16) {
    return (uint32_t)(row * 64 + ((c16 ^ ((row >> 1) & 3)) << 4));
}

// ---------------- setup: discretize in fp64, build split W1 -----------------
__global__ void setup_kernel(const float* __restrict__ Lre, const float* __restrict__ Lim,
                             const float* __restrict__ Bre, const float* __restrict__ Bim,
                             const float* __restrict__ log_step) {
    int p = blockIdx.x;
    __shared__ float2 s_f;
    if (threadIdx.x == 0) {
        double lr = (double)Lre[p], li = (double)Lim[p];
        double dt = exp((double)log_step[p]);
        double mag = exp(lr * dt);
        double lam_r = mag * cos(li * dt);
        double lam_i = mag * sin(li * dt);
        d_Lam[p] = make_float2((float)lam_r, (float)lam_i);
        double nr = lam_r - 1.0, ni = lam_i;
        double den = lr * lr + li * li;
        s_f = make_float2((float)((nr * lr + ni * li) / den),
                          (float)((ni * lr - nr * li) / den));
        double pr = lam_r, pi = lam_i;
        #pragma unroll
        for (int i = 0; i < 7; i++) { double r2 = pr*pr - pi*pi, i2 = 2.0*pr*pi; pr = r2; pi = i2; }
        d_LamPow[p] = make_float2((float)pr, (float)pi);
    }
    __syncthreads();
    float fr = s_f.x, fi = s_f.y;
    for (int h = threadIdx.x; h < HH; h += blockDim.x) {
        float br = Bre[p * HH + h], bi = Bim[p * HH + h];
        float wr = fr * br - fi * bi;
        float wi = fr * bi + fi * br;
        split_bf16(wr, d_W1hi[p * K1 + h],        d_W1lo[p * K1 + h]);
        split_bf16(wi, d_W1hi[(PP + p) * K1 + h], d_W1lo[(PP + p) * K1 + h]);
    }
}

__global__ void w2_kernel(const float* __restrict__ Cre, const float* __restrict__ Cim) {
    int idx = blockIdx.x * blockDim.x + threadIdx.x;
    int h = idx >> 9, p = idx & (PP - 1);
    split_bf16( 2.0f * Cre[h * PP + p], d_W2hi[h * K2 + p],      d_W2lo[h * K2 + p]);
    split_bf16(-2.0f * Cim[h * PP + p], d_W2hi[h * K2 + PP + p], d_W2lo[h * K2 + PP + p]);
}

__global__ void usplit_kernel(const float* __restrict__ u) {
    size_t i = (size_t)blockIdx.x * blockDim.x + threadIdx.x;
    float v = u[i];
    split_bf16(v, d_Uhi[i], d_Ulo[i]);
}

// ---------------- HMMA split-bf16 GEMM: C[m,n] = sum_k A[m,k]*W[n,k] --------
// 128x128 CTA tile, BK=32, 8 warps of 64x32.
// 3-stage cp.async pipeline, XOR-swizzled 64B-row tiles, 1 barrier/chunk.
#define TILE_B  (128 * 64)               // 8192 B
#define STAGE_B (4 * TILE_B)             // Ahi, Alo, Whi, Wlo = 32768 B
#define NSTAGE  3
#define GSMEM   (NSTAGE * STAGE_B)       // 98304 B

__global__ void __launch_bounds__(256, 2)
hmma_gemm(const __nv_bfloat16* __restrict__ Ahi, const __nv_bfloat16* __restrict__ Alo,
          const __nv_bfloat16* __restrict__ Whi, const __nv_bfloat16* __restrict__ Wlo,
          float* __restrict__ C, int N, int K) {
    extern __shared__ char smem[];
    const uint32_t sb = smem_u32(smem);
    const int tid = threadIdx.x;
    const int wid = tid >> 5, lane = tid & 31;
    const int wm = wid >> 2, wn = wid & 3;       // warp tile: rows wm*64, cols wn*32
    const int m0 = blockIdx.y * 128, n0 = blockIdx.x * 128;

    const char* srcs[4] = {
        (const char*)(Ahi + (size_t)m0 * K), (const char*)(Alo + (size_t)m0 * K),
        (const char*)(Whi + (size_t)n0 * K), (const char*)(Wlo + (size_t)n0 * K) };
    const size_t rstride = (size_t)K * 2;

    const int gtile = tid >> 6;         // which of the 4 tiles this thread loads
    const int lt    = tid & 63;

    auto prefetch = [&](int stage, int ci) {
        const char* src = srcs[gtile] + (size_t)ci * 64;      // 32 bf16 per k-chunk
        uint32_t tb = sb + stage * STAGE_B + gtile * TILE_B;
        #pragma unroll
        for (int i = 0; i < 8; i++) {
            int chunk = lt + i * 64;             // 0..511
            int row = chunk >> 2, c = chunk & 3;
            cp16(tb + sw_off(row, c), src + (size_t)row * rstride + c * 16);
        }
    };

    float acc[4][4][4];
    #pragma unroll
    for (int i = 0; i < 4; i++)
        #pragma unroll
        for (int j = 0; j < 4; j++)
            #pragma unroll
            for (int q = 0; q < 4; q++) acc[i][j][q] = 0.f;

    const int nch = K / 32;
    prefetch(0, 0); CP_COMMIT();
    prefetch(1, 1); CP_COMMIT();

    // fragment address components (per lane)
    const int a_row = lane & 15;
    const int a_c   = lane >> 4;                  // +0 or +1 16B column
    const int b_row = (lane & 7) + ((lane >> 4) & 1) * 8;
    const int b_c   = (lane >> 3) & 1;

    int s = 0;
    for (int ci = 0; ci < nch; ci++) {
        CP_WAIT(1);
        __syncthreads();

        uint32_t sAhi = sb + s * STAGE_B + 0 * TILE_B;
        uint32_t sAlo = sb + s * STAGE_B + 1 * TILE_B;
        uint32_t sWhi = sb + s * STAGE_B + 2 * TILE_B;
        uint32_t sWlo = sb + s * STAGE_B + 3 * TILE_B;

        #pragma unroll
        for (int ks = 0; ks < 2; ks++) {
            // B fragments for this k-step
            uint32_t bhi[4][2], blo[4][2];
            #pragma unroll
            for (int np = 0; np < 2; np++) {
                int brow = wn * 32 + np * 16 + b_row;
                uint32_t off = sw_off(brow, ks * 2 + b_c);
                uint32_t r[4];
                ldm_x4(sWhi + off, r);
                bhi[np*2][0] = r[0]; bhi[np*2][1] = r[1];
                bhi[np*2+1][0] = r[2]; bhi[np*2+1][1] = r[3];
                ldm_x4(sWlo + off, r);
                blo[np*2][0] = r[0]; blo[np*2][1] = r[1];
                blo[np*2+1][0] = r[2]; blo[np*2+1][1] = r[3];
            }
            // A fragments loaded per-mt, MMAs fired immediately
            #pragma unroll
            for (int mt = 0; mt < 4; mt++) {
                int arow = wm * 64 + mt * 16 + a_row;
                uint32_t off = sw_off(arow, ks * 2 + a_c);
                uint32_t ahi[4], alo[4];
                ldm_x4(sAhi + off, ahi);
                ldm_x4(sAlo + off, alo);
                #pragma unroll
                for (int nt = 0; nt < 4; nt++) {
                    hmma(acc[mt][nt], ahi, bhi[nt]);
                    hmma(acc[mt][nt], ahi, blo[nt]);
                    hmma(acc[mt][nt], alo, bhi[nt]);
                }
            }
        }
        // prefetch 2 chunks ahead into the stage freed by this iteration's barrier
        if (ci + 2 < nch) prefetch((s + 2) % NSTAGE, ci + 2);
        CP_COMMIT();
        s = (s + 1 == NSTAGE) ? 0 : s + 1;
    }

    // epilogue
    #pragma unroll
    for (int mt = 0; mt < 4; mt++) {
        int r = m0 + wm * 64 + mt * 16 + (lane >> 2);
        #pragma unroll
        for (int nt = 0; nt < 4; nt++) {
            int c = n0 + wn * 32 + nt * 8 + (lane & 3) * 2;
            *(float2*)(C + (size_t)r * N + c)       = make_float2(acc[mt][nt][0], acc[mt][nt][1]);
            *(float2*)(C + (size_t)(r + 8) * N + c) = make_float2(acc[mt][nt][2], acc[mt][nt][3]);
        }
    }
}

// ---------------- chunked complex scan over L --------------------------------
__global__ void scan_phaseA() {
    int idx = blockIdx.x * blockDim.x + threadIdx.x;
    int p = idx & (PP - 1);
    int c = (idx >> 9) & (NCHUNK - 1);
    int b = idx >> 14;
    float2 lam = d_Lam[p];
    float xr = 0.f, xi = 0.f;
    size_t base = ((size_t)b * LL + (size_t)c * CLEN) * N1;
    const float* Xr = d_X + base + p;
    const float* Xi = d_X + base + PP + p;
    #pragma unroll 4
    for (int j = 0; j < CLEN; j++) {
        float br = Xr[(size_t)j * N1];
        float bi = Xi[(size_t)j * N1];
        float nr = fmaf(lam.x, xr, fmaf(-lam.y, xi, br));
        float ni = fmaf(lam.x, xi, fmaf( lam.y, xr, bi));
        xr = nr; xi = ni;
    }
    d_yend[(b * NCHUNK + c) * PP + p] = make_float2(xr, xi);
}

__global__ void scan_phaseB() {
    int idx = blockIdx.x * blockDim.x + threadIdx.x;
    int p = idx & (PP - 1);
    int b = idx >> 9;
    float2 pw = d_LamPow[p];
    float cr = 0.f, ci = 0.f;
    #pragma unroll
    for (int c = 0; c < NCHUNK; c++) {
        d_cin[(b * NCHUNK + c) * PP + p] = make_float2(cr, ci);
        float2 ye = d_yend[(b * NCHUNK + c) * PP + p];
        float nr = fmaf(pw.x, cr, fmaf(-pw.y, ci, ye.x));
        float ni = fmaf(pw.x, ci, fmaf( pw.y, cr, ye.y));
        cr = nr; ci = ni;
    }
}

__global__ void scan_phaseC() {
    int idx = blockIdx.x * blockDim.x + threadIdx.x;
    int p = idx & (PP - 1);
    int c = (idx >> 9) & (NCHUNK - 1);
    int b = idx >> 14;
    float2 lam = d_Lam[p];
    float2 c0 = d_cin[(b * NCHUNK + c) * PP + p];
    float xr = c0.x, xi = c0.y;
    size_t mrow = (size_t)b * LL + (size_t)c * CLEN;
    const float* Xr = d_X + mrow * N1 + p;
    const float* Xi = d_X + mrow * N1 + PP + p;
    __nv_bfloat16* Hr = d_Xhi + mrow * K2 + p;
    __nv_bfloat16* Hi = d_Xhi + mrow * K2 + PP + p;
    __nv_bfloat16* Lr = d_Xlo + mrow * K2 + p;
    __nv_bfloat16* Li = d_Xlo + mrow * K2 + PP + p;
    #pragma unroll 4
    for (int j = 0; j < CLEN; j++) {
        float br = Xr[(size_t)j * N1];
        float bi = Xi[(size_t)j * N1];
        float nr = fmaf(lam.x, xr, fmaf(-lam.y, xi, br));
        float ni = fmaf(lam.x, xi, fmaf( lam.y, xr, bi));
        xr = nr; xi = ni;
        __nv_bfloat16 h, l;
        split_bf16(xr, h, l); Hr[(size_t)j * K2] = h; Lr[(size_t)j * K2] = l;
        split_bf16(xi, h, l); Hi[(size_t)j * K2] = h; Li[(size_t)j * K2] = l;
    }
}

// ---------------- launch -----------------------------------------------------
extern "C" void kernel_launch(void* const* d_in, const int* in_sizes, int n_in,
                              void* d_out, int out_size) {
    const float* Lre      = (const float*)d_in[0];
    const float* Lim      = (const float*)d_in[1];
    const float* Bre      = (const float*)d_in[2];
    const float* Bim      = (const float*)d_in[3];
    const float* Cre      = (const float*)d_in[4];
    const float* Cim      = (const float*)d_in[5];
    const float* log_step = (const float*)d_in[6];
    const float* u        = (const float*)d_in[7];
    float* out = (float*)d_out;

    float *Xp;
    __nv_bfloat16 *Uhi, *Ulo, *Xhi, *Xlo, *W1h, *W1l, *W2h, *W2l;
    cudaGetSymbolAddress((void**)&Xp,  d_X);
    cudaGetSymbolAddress((void**)&Uhi, d_Uhi);
    cudaGetSymbolAddress((void**)&Ulo, d_Ulo);
    cudaGetSymbolAddress((void**)&Xhi, d_Xhi);
    cudaGetSymbolAddress((void**)&Xlo, d_Xlo);
    cudaGetSymbolAddress((void**)&W1h, d_W1hi);
    cudaGetSymbolAddress((void**)&W1l, d_W1lo);
    cudaGetSymbolAddress((void**)&W2h, d_W2hi);
    cudaGetSymbolAddress((void**)&W2l, d_W2lo);

    cudaFuncSetAttribute(hmma_gemm, cudaFuncAttributeMaxDynamicSharedMemorySize, GSMEM);

    setup_kernel<<<PP, 256>>>(Lre, Lim, Bre, Bim, log_step);
    w2_kernel<<<(HH * PP) / 256, 256>>>(Cre, Cim);
    usplit_kernel<<<(int)(((size_t)MM * K1) / 256), 256>>>(u);

    // GEMM1: Bu(re|im) = u @ W1^T -> d_X fp32 (M x 1024)
    hmma_gemm<<<dim3(N1 / 128, MM / 128), 256, GSMEM>>>(Uhi, Ulo, W1h, W1l, Xp, N1, K1);

    // chunked complex scan; phaseC emits split-bf16 xs
    scan_phaseA<<<(BB * NCHUNK * PP) / 256, 256>>>();
    scan_phaseB<<<(BB * PP) / 256, 256>>>();
    scan_phaseC<<<(BB * NCHUNK * PP) / 256, 256>>>();

    // GEMM2: ys = xs @ W2^T -> out (M x 512)
    hmma_gemm<<<dim3(N2 / 128, MM / 128), 256, GSMEM>>>(Xhi, Xlo, W2h, W2l, out, N2, K2);
}

// round 7
// speedup vs baseline: 3.6628x; 1.3675x over previous
#include <cuda_runtime.h>
#include <cuda_fp16.h>
#include <math.h>
#include <stdint.h>

// Problem constants
#define BB    8
#define LL    4096
#define HH    512
#define PP    512
#define MM    (BB*LL)     // 32768 tokens
#define N1    (2*PP)      // 1024  (Bu_re | Bu_im)
#define K1    HH          // 512
#define N2    HH          // 512
#define K2    (2*PP)      // 1024  (x_re | x_im)
#define NCHUNK 32
#define CLEN   128        // LL / NCHUNK

// ---------------- static device scratch -------------------------------------
__device__ float   d_X  [(size_t)MM * N1];   // Bu fp32 (128MB)
__device__ __half  d_Uh [(size_t)MM * K1];   // u rounded to fp16 (32MB)
__device__ __half  d_Xh [(size_t)MM * K2];   // xs rounded to fp16 (64MB)
__device__ __half  d_W1hi[N1 * K1];          // B_bar folded, fp16 split
__device__ __half  d_W1lo[N1 * K1];
__device__ __half  d_W2hi[N2 * K2];          // [2C_re | -2C_im], fp16 split
__device__ __half  d_W2lo[N2 * K2];
__device__ float2 d_Lam[PP];
__device__ float2 d_LamPow[PP];
__device__ float2 d_yend[BB * NCHUNK * PP];
__device__ float2 d_cin [BB * NCHUNK * PP];

// ---------------- helpers ----------------------------------------------------
__device__ __forceinline__ uint32_t smem_u32(const void* p) {
    uint32_t a;
    asm("{ .reg .u64 t; cvta.to.shared.u64 t, %1; cvt.u32.u64 %0, t; }" : "=r"(a) : "l"(p));
    return a;
}
__device__ __forceinline__ void cp16(uint32_t saddr, const void* g) {
    asm volatile("cp.async.cg.shared.global [%0], [%1], 16;" :: "r"(saddr), "l"(g));
}
#define CP_COMMIT() asm volatile("cp.async.commit_group;" ::: "memory")
#define CP_WAIT(n)  asm volatile("cp.async.wait_group %0;" :: "n"(n) : "memory")

__device__ __forceinline__ void ldm_x4(uint32_t addr, uint32_t* r) {
    asm volatile("ldmatrix.sync.aligned.m8n8.x4.shared.b16 {%0,%1,%2,%3}, [%4];"
                 : "=r"(r[0]), "=r"(r[1]), "=r"(r[2]), "=r"(r[3]) : "r"(addr));
}
__device__ __forceinline__ void hmma(float* c, const uint32_t* a, const uint32_t* b) {
    asm volatile(
        "mma.sync.aligned.m16n8k16.row.col.f32.f16.f16.f32 "
        "{%0,%1,%2,%3}, {%4,%5,%6,%7}, {%8,%9}, {%0,%1,%2,%3};"
        : "+f"(c[0]), "+f"(c[1]), "+f"(c[2]), "+f"(c[3])
        : "r"(a[0]), "r"(a[1]), "r"(a[2]), "r"(a[3]), "r"(b[0]), "r"(b[1]));
}
__device__ __forceinline__ void split_fp16(float x, __half& h, __half& l) {
    h = __float2half(x);
    l = __float2half(x - __half2float(h));
}

// XOR swizzle inside a 128-row x 64B tile: (row, c16) -> byte offset
__device__ __forceinline__ uint32_t sw_off(int row, int c16) {
    return (uint32_t)(row * 64 + ((c16 ^ ((row >> 1) & 3)) << 4));
}

// ---------------- setup: discretize in fp64, build split W1 -----------------
__global__ void setup_kernel(const float* __restrict__ Lre, const float* __restrict__ Lim,
                             const float* __restrict__ Bre, const float* __restrict__ Bim,
                             const float* __restrict__ log_step) {
    int p = blockIdx.x;
    __shared__ float2 s_f;
    if (threadIdx.x == 0) {
        double lr = (double)Lre[p], li = (double)Lim[p];
        double dt = exp((double)log_step[p]);
        double mag = exp(lr * dt);
        double lam_r = mag * cos(li * dt);
        double lam_i = mag * sin(li * dt);
        d_Lam[p] = make_float2((float)lam_r, (float)lam_i);
        double nr = lam_r - 1.0, ni = lam_i;
        double den = lr * lr + li * li;
        s_f = make_float2((float)((nr * lr + ni * li) / den),
                          (float)((ni * lr - nr * li) / den));
        double pr = lam_r, pi = lam_i;
        #pragma unroll
        for (int i = 0; i < 7; i++) { double r2 = pr*pr - pi*pi, i2 = 2.0*pr*pi; pr = r2; pi = i2; }
        d_LamPow[p] = make_float2((float)pr, (float)pi);
    }
    __syncthreads();
    float fr = s_f.x, fi = s_f.y;
    for (int h = threadIdx.x; h < HH; h += blockDim.x) {
        float br = Bre[p * HH + h], bi = Bim[p * HH + h];
        float wr = fr * br - fi * bi;
        float wi = fr * bi + fi * br;
        split_fp16(wr, d_W1hi[p * K1 + h],        d_W1lo[p * K1 + h]);
        split_fp16(wi, d_W1hi[(PP + p) * K1 + h], d_W1lo[(PP + p) * K1 + h]);
    }
}

__global__ void w2_kernel(const float* __restrict__ Cre, const float* __restrict__ Cim) {
    int idx = blockIdx.x * blockDim.x + threadIdx.x;
    int h = idx >> 9, p = idx & (PP - 1);
    split_fp16( 2.0f * Cre[h * PP + p], d_W2hi[h * K2 + p],      d_W2lo[h * K2 + p]);
    split_fp16(-2.0f * Cim[h * PP + p], d_W2hi[h * K2 + PP + p], d_W2lo[h * K2 + PP + p]);
}

__global__ void uconv_kernel(const float* __restrict__ u) {
    size_t i = (size_t)blockIdx.x * blockDim.x + threadIdx.x;
    d_Uh[i] = __float2half(u[i]);
}

// ---------------- HMMA fp16 GEMM: C[m,n] = sum_k A[m,k]*(Whi+Wlo)[n,k] ------
// 128x128 CTA tile, BK=32, 8 warps of 64x32.
// 4-stage cp.async pipeline, XOR-swizzled 64B-row tiles, 1 barrier/chunk.
// A rounded fp16 (data); W split into hi/lo fp16 (weights, near-exact).
#define TILE_B  (128 * 64)               // 8192 B
#define STAGE_B (3 * TILE_B)             // A, Whi, Wlo = 24576 B
#define NSTAGE  4
#define GSMEM   (NSTAGE * STAGE_B)       // 98304 B

__global__ void __launch_bounds__(256, 2)
hmma_gemm(const __half* __restrict__ A,
          const __half* __restrict__ Whi, const __half* __restrict__ Wlo,
          float* __restrict__ C, int N, int K) {
    extern __shared__ char smem[];
    const uint32_t sb = smem_u32(smem);
    const int tid = threadIdx.x;
    const int wid = tid >> 5, lane = tid & 31;
    const int wm = wid >> 2, wn = wid & 3;       // warp tile: rows wm*64, cols wn*32
    const int m0 = blockIdx.y * 128, n0 = blockIdx.x * 128;

    const char* srcs[3] = {
        (const char*)(A   + (size_t)m0 * K),
        (const char*)(Whi + (size_t)n0 * K),
        (const char*)(Wlo + (size_t)n0 * K) };
    const size_t rstride = (size_t)K * 2;

    auto prefetch = [&](int stage, int ci) {
        #pragma unroll
        for (int it = 0; it < 6; it++) {
            int id = it * 256 + tid;            // 0..1535
            int t = id >> 9;                    // tile 0..2
            int w = id & 511;
            int row = w >> 2, c = w & 3;
            cp16(sb + stage * STAGE_B + t * TILE_B + sw_off(row, c),
                 srcs[t] + (size_t)ci * 64 + (size_t)row * rstride + c * 16);
        }
    };

    float acc[4][4][4];
    #pragma unroll
    for (int i = 0; i < 4; i++)
        #pragma unroll
        for (int j = 0; j < 4; j++)
            #pragma unroll
            for (int q = 0; q < 4; q++) acc[i][j][q] = 0.f;

    const int nch = K / 32;
    prefetch(0, 0); CP_COMMIT();
    prefetch(1, 1); CP_COMMIT();
    prefetch(2, 2); CP_COMMIT();

    // fragment address components (per lane)
    const int a_row = lane & 15;
    const int a_c   = lane >> 4;                  // +0 or +1 16B column
    const int b_row = (lane & 7) + ((lane >> 4) & 1) * 8;
    const int b_c   = (lane >> 3) & 1;

    int s = 0;
    for (int ci = 0; ci < nch; ci++) {
        CP_WAIT(2);
        __syncthreads();

        uint32_t sA   = sb + s * STAGE_B + 0 * TILE_B;
        uint32_t sWhi = sb + s * STAGE_B + 1 * TILE_B;
        uint32_t sWlo = sb + s * STAGE_B + 2 * TILE_B;

        #pragma unroll
        for (int ks = 0; ks < 2; ks++) {
            // B fragments for this k-step
            uint32_t whi[4][2], wlo[4][2];
            #pragma unroll
            for (int np = 0; np < 2; np++) {
                int brow = wn * 32 + np * 16 + b_row;
                uint32_t off = sw_off(brow, ks * 2 + b_c);
                uint32_t r[4];
                ldm_x4(sWhi + off, r);
                whi[np*2][0] = r[0]; whi[np*2][1] = r[1];
                whi[np*2+1][0] = r[2]; whi[np*2+1][1] = r[3];
                ldm_x4(sWlo + off, r);
                wlo[np*2][0] = r[0]; wlo[np*2][1] = r[1];
                wlo[np*2+1][0] = r[2]; wlo[np*2+1][1] = r[3];
            }
            // A fragment per mt; two independent nt-passes (dep distance 4)
            #pragma unroll
            for (int mt = 0; mt < 4; mt++) {
                int arow = wm * 64 + mt * 16 + a_row;
                uint32_t off = sw_off(arow, ks * 2 + a_c);
                uint32_t a[4];
                ldm_x4(sA + off, a);
                #pragma unroll
                for (int nt = 0; nt < 4; nt++) hmma(acc[mt][nt], a, whi[nt]);
                #pragma unroll
                for (int nt = 0; nt < 4; nt++) hmma(acc[mt][nt], a, wlo[nt]);
            }
        }
        // prefetch 3 chunks ahead into the stage freed by this iteration
        if (ci + 3 < nch) prefetch((s + 3) & 3, ci + 3);
        CP_COMMIT();
        s = (s + 1) & 3;
    }

    // epilogue
    #pragma unroll
    for (int mt = 0; mt < 4; mt++) {
        int r = m0 + wm * 64 + mt * 16 + (lane >> 2);
        #pragma unroll
        for (int nt = 0; nt < 4; nt++) {
            int c = n0 + wn * 32 + nt * 8 + (lane & 3) * 2;
            *(float2*)(C + (size_t)r * N + c)       = make_float2(acc[mt][nt][0], acc[mt][nt][1]);
            *(float2*)(C + (size_t)(r + 8) * N + c) = make_float2(acc[mt][nt][2], acc[mt][nt][3]);
        }
    }
}

// ---------------- chunked complex scan over L --------------------------------
__global__ void scan_phaseA() {
    int idx = blockIdx.x * blockDim.x + threadIdx.x;
    int p = idx & (PP - 1);
    int c = (idx >> 9) & (NCHUNK - 1);
    int b = idx >> 14;
    float2 lam = d_Lam[p];
    float xr = 0.f, xi = 0.f;
    size_t base = ((size_t)b * LL + (size_t)c * CLEN) * N1;
    const float* Xr = d_X + base + p;
    const float* Xi = d_X + base + PP + p;
    #pragma unroll 4
    for (int j = 0; j < CLEN; j++) {
        float br = Xr[(size_t)j * N1];
        float bi = Xi[(size_t)j * N1];
        float nr = fmaf(lam.x, xr, fmaf(-lam.y, xi, br));
        float ni = fmaf(lam.x, xi, fmaf( lam.y, xr, bi));
        xr = nr; xi = ni;
    }
    d_yend[(b * NCHUNK + c) * PP + p] = make_float2(xr, xi);
}

__global__ void scan_phaseB() {
    int idx = blockIdx.x * blockDim.x + threadIdx.x;
    int p = idx & (PP - 1);
    int b = idx >> 9;
    float2 pw = d_LamPow[p];
    float cr = 0.f, ci = 0.f;
    #pragma unroll
    for (int c = 0; c < NCHUNK; c++) {
        d_cin[(b * NCHUNK + c) * PP + p] = make_float2(cr, ci);
        float2 ye = d_yend[(b * NCHUNK + c) * PP + p];
        float nr = fmaf(pw.x, cr, fmaf(-pw.y, ci, ye.x));
        float ni = fmaf(pw.x, ci, fmaf( pw.y, cr, ye.y));
        cr = nr; ci = ni;
    }
}

// phaseC: apply carry-in, emit xs rounded to fp16 for GEMM2
__global__ void scan_phaseC() {
    int idx = blockIdx.x * blockDim.x + threadIdx.x;
    int p = idx & (PP - 1);
    int c = (idx >> 9) & (NCHUNK - 1);
    int b = idx >> 14;
    float2 lam = d_Lam[p];
    float2 c0 = d_cin[(b * NCHUNK + c) * PP + p];
    float xr = c0.x, xi = c0.y;
    size_t mrow = (size_t)b * LL + (size_t)c * CLEN;
    const float* Xr = d_X + mrow * N1 + p;
    const float* Xi = d_X + mrow * N1 + PP + p;
    __half* Hr = d_Xh + mrow * K2 + p;
    __half* Hi = d_Xh + mrow * K2 + PP + p;
    #pragma unroll 4
    for (int j = 0; j < CLEN; j++) {
        float br = Xr[(size_t)j * N1];
        float bi = Xi[(size_t)j * N1];
        float nr = fmaf(lam.x, xr, fmaf(-lam.y, xi, br));
        float ni = fmaf(lam.x, xi, fmaf( lam.y, xr, bi));
        xr = nr; xi = ni;
        Hr[(size_t)j * K2] = __float2half(xr);
        Hi[(size_t)j * K2] = __float2half(xi);
    }
}

// ---------------- launch -----------------------------------------------------
extern "C" void kernel_launch(void* const* d_in, const int* in_sizes, int n_in,
                              void* d_out, int out_size) {
    const float* Lre      = (const float*)d_in[0];
    const float* Lim      = (const float*)d_in[1];
    const float* Bre      = (const float*)d_in[2];
    const float* Bim      = (const float*)d_in[3];
    const float* Cre      = (const float*)d_in[4];
    const float* Cim      = (const float*)d_in[5];
    const float* log_step = (const float*)d_in[6];
    const float* u        = (const float*)d_in[7];
    float* out = (float*)d_out;

    float *Xp;
    __half *Uh, *Xh, *W1h, *W1l, *W2h, *W2l;
    cudaGetSymbolAddress((void**)&Xp,  d_X);
    cudaGetSymbolAddress((void**)&Uh,  d_Uh);
    cudaGetSymbolAddress((void**)&Xh,  d_Xh);
    cudaGetSymbolAddress((void**)&W1h, d_W1hi);
    cudaGetSymbolAddress((void**)&W1l, d_W1lo);
    cudaGetSymbolAddress((void**)&W2h, d_W2hi);
    cudaGetSymbolAddress((void**)&W2l, d_W2lo);

    cudaFuncSetAttribute(hmma_gemm, cudaFuncAttributeMaxDynamicSharedMemorySize, GSMEM);

    setup_kernel<<<PP, 256>>>(Lre, Lim, Bre, Bim, log_step);
    w2_kernel<<<(HH * PP) / 256, 256>>>(Cre, Cim);
    uconv_kernel<<<(int)(((size_t)MM * K1) / 256), 256>>>(u);

    // GEMM1: Bu(re|im) = u @ W1^T -> d_X fp32 (M x 1024)
    hmma_gemm<<<dim3(N1 / 128, MM / 128), 256, GSMEM>>>(Uh, W1h, W1l, Xp, N1, K1);

    // chunked complex scan; phaseC emits fp16 xs
    scan_phaseA<<<(BB * NCHUNK * PP) / 256, 256>>>();
    scan_phaseB<<<(BB * PP) / 256, 256>>>();
    scan_phaseC<<<(BB * NCHUNK * PP) / 256, 256>>>();

    // GEMM2: ys = xs @ W2^T -> out (M x 512)
    hmma_gemm<<<dim3(N2 / 128, MM / 128), 256, GSMEM>>>(Xh, W2h, W2l, out, N2, K2);
}

// round 8
// speedup vs baseline: 3.7767x; 1.0311x over previous
#include <cuda_runtime.h>
#include <cuda_fp16.h>
#include <math.h>
#include <stdint.h>

// Problem constants
#define BB    8
#define LL    4096
#define HH    512
#define PP    512
#define MM    (BB*LL)     // 32768 tokens
#define N1    (2*PP)      // 1024  (Bu_re | Bu_im)
#define K1    HH          // 512
#define N2    HH          // 512
#define K2    (2*PP)      // 1024  (x_re | x_im)
#define NCHUNK 32
#define CLEN   128        // LL / NCHUNK

// ---------------- static device scratch -------------------------------------
__device__ __half  d_Bu [(size_t)MM * N1];   // Bu fp16 (64MB)
__device__ __half  d_Uh [(size_t)MM * K1];   // u rounded to fp16 (32MB)
__device__ __half  d_Xh [(size_t)MM * K2];   // xs rounded to fp16 (64MB)
__device__ __half  d_W1hi[N1 * K1];          // B_bar folded, fp16 split
__device__ __half  d_W1lo[N1 * K1];
__device__ __half  d_W2hi[N2 * K2];          // [2C_re | -2C_im], fp16 split
__device__ __half  d_W2lo[N2 * K2];
__device__ float2 d_Lam[PP];
__device__ float2 d_LamPow[PP];
__device__ float2 d_yend[BB * NCHUNK * PP];
__device__ float2 d_cin [BB * NCHUNK * PP];

// ---------------- helpers ----------------------------------------------------
__device__ __forceinline__ uint32_t smem_u32(const void* p) {
    uint32_t a;
    asm("{ .reg .u64 t; cvta.to.shared.u64 t, %1; cvt.u32.u64 %0, t; }" : "=r"(a) : "l"(p));
    return a;
}
__device__ __forceinline__ void cp16(uint32_t saddr, const void* g) {
    asm volatile("cp.async.cg.shared.global [%0], [%1], 16;" :: "r"(saddr), "l"(g));
}
#define CP_COMMIT() asm volatile("cp.async.commit_group;" ::: "memory")
#define CP_WAIT(n)  asm volatile("cp.async.wait_group %0;" :: "n"(n) : "memory")

__device__ __forceinline__ void ldm_x4(uint32_t addr, uint32_t* r) {
    asm volatile("ldmatrix.sync.aligned.m8n8.x4.shared.b16 {%0,%1,%2,%3}, [%4];"
                 : "=r"(r[0]), "=r"(r[1]), "=r"(r[2]), "=r"(r[3]) : "r"(addr));
}
__device__ __forceinline__ void hmma(float* c, const uint32_t* a, const uint32_t* b) {
    asm volatile(
        "mma.sync.aligned.m16n8k16.row.col.f32.f16.f16.f32 "
        "{%0,%1,%2,%3}, {%4,%5,%6,%7}, {%8,%9}, {%0,%1,%2,%3};"
        : "+f"(c[0]), "+f"(c[1]), "+f"(c[2]), "+f"(c[3])
        : "r"(a[0]), "r"(a[1]), "r"(a[2]), "r"(a[3]), "r"(b[0]), "r"(b[1]));
}
__device__ __forceinline__ void split_fp16(float x, __half& h, __half& l) {
    h = __float2half(x);
    l = __float2half(x - __half2float(h));
}

// XOR swizzle inside a 128-row x 64B tile: (row, c16) -> byte offset
__device__ __forceinline__ uint32_t sw_off(int row, int c16) {
    return (uint32_t)(row * 64 + ((c16 ^ ((row >> 1) & 3)) << 4));
}

// ---------------- setup: discretize in fp64, build split W1 -----------------
__global__ void setup_kernel(const float* __restrict__ Lre, const float* __restrict__ Lim,
                             const float* __restrict__ Bre, const float* __restrict__ Bim,
                             const float* __restrict__ log_step) {
    int p = blockIdx.x;
    __shared__ float2 s_f;
    if (threadIdx.x == 0) {
        double lr = (double)Lre[p], li = (double)Lim[p];
        double dt = exp((double)log_step[p]);
        double mag = exp(lr * dt);
        double lam_r = mag * cos(li * dt);
        double lam_i = mag * sin(li * dt);
        d_Lam[p] = make_float2((float)lam_r, (float)lam_i);
        double nr = lam_r - 1.0, ni = lam_i;
        double den = lr * lr + li * li;
        s_f = make_float2((float)((nr * lr + ni * li) / den),
                          (float)((ni * lr - nr * li) / den));
        double pr = lam_r, pi = lam_i;
        #pragma unroll
        for (int i = 0; i < 7; i++) { double r2 = pr*pr - pi*pi, i2 = 2.0*pr*pi; pr = r2; pi = i2; }
        d_LamPow[p] = make_float2((float)pr, (float)pi);
    }
    __syncthreads();
    float fr = s_f.x, fi = s_f.y;
    for (int h = threadIdx.x; h < HH; h += blockDim.x) {
        float br = Bre[p * HH + h], bi = Bim[p * HH + h];
        float wr = fr * br - fi * bi;
        float wi = fr * bi + fi * br;
        split_fp16(wr, d_W1hi[p * K1 + h],        d_W1lo[p * K1 + h]);
        split_fp16(wi, d_W1hi[(PP + p) * K1 + h], d_W1lo[(PP + p) * K1 + h]);
    }
}

__global__ void w2_kernel(const float* __restrict__ Cre, const float* __restrict__ Cim) {
    int idx = blockIdx.x * blockDim.x + threadIdx.x;
    int h = idx >> 9, p = idx & (PP - 1);
    split_fp16( 2.0f * Cre[h * PP + p], d_W2hi[h * K2 + p],      d_W2lo[h * K2 + p]);
    split_fp16(-2.0f * Cim[h * PP + p], d_W2hi[h * K2 + PP + p], d_W2lo[h * K2 + PP + p]);
}

__global__ void uconv_kernel(const float* __restrict__ u) {
    size_t i = (size_t)blockIdx.x * blockDim.x + threadIdx.x;
    d_Uh[i] = __float2half(u[i]);
}

// ---------------- HMMA fp16 GEMM: C[m,n] = sum_k A[m,k]*(Whi+Wlo)[n,k] ------
// 128x128 CTA tile, BK=32, 8 warps of 64x32.
// 4-stage cp.async pipeline, XOR-swizzled 64B-row tiles, 1 barrier/chunk.
// OUT_HALF: write C as fp16 (GEMM1) or fp32 (GEMM2).
#define TILE_B  (128 * 64)               // 8192 B
#define STAGE_B (3 * TILE_B)             // A, Whi, Wlo = 24576 B
#define NSTAGE  4
#define GSMEM   (NSTAGE * STAGE_B)       // 98304 B

template <int OUT_HALF>
__global__ void __launch_bounds__(256, 2)
hmma_gemm(const __half* __restrict__ A,
          const __half* __restrict__ Whi, const __half* __restrict__ Wlo,
          void* __restrict__ Cv, int N, int K) {
    extern __shared__ char smem[];
    const uint32_t sb = smem_u32(smem);
    const int tid = threadIdx.x;
    const int wid = tid >> 5, lane = tid & 31;
    const int wm = wid >> 2, wn = wid & 3;       // warp tile: rows wm*64, cols wn*32
    const int m0 = blockIdx.y * 128, n0 = blockIdx.x * 128;

    const char* srcs[3] = {
        (const char*)(A   + (size_t)m0 * K),
        (const char*)(Whi + (size_t)n0 * K),
        (const char*)(Wlo + (size_t)n0 * K) };
    const size_t rstride = (size_t)K * 2;

    auto prefetch = [&](int stage, int ci) {
        #pragma unroll
        for (int it = 0; it < 6; it++) {
            int id = it * 256 + tid;            // 0..1535
            int t = id >> 9;                    // tile 0..2
            int w = id & 511;
            int row = w >> 2, c = w & 3;
            cp16(sb + stage * STAGE_B + t * TILE_B + sw_off(row, c),
                 srcs[t] + (size_t)ci * 64 + (size_t)row * rstride + c * 16);
        }
    };

    float acc[4][4][4];
    #pragma unroll
    for (int i = 0; i < 4; i++)
        #pragma unroll
        for (int j = 0; j < 4; j++)
            #pragma unroll
            for (int q = 0; q < 4; q++) acc[i][j][q] = 0.f;

    const int nch = K / 32;
    prefetch(0, 0); CP_COMMIT();
    prefetch(1, 1); CP_COMMIT();
    prefetch(2, 2); CP_COMMIT();

    // fragment address components (per lane)
    const int a_row = lane & 15;
    const int a_c   = lane >> 4;                  // +0 or +1 16B column
    const int b_row = (lane & 7) + ((lane >> 4) & 1) * 8;
    const int b_c   = (lane >> 3) & 1;

    int s = 0;
    for (int ci = 0; ci < nch; ci++) {
        CP_WAIT(2);
        __syncthreads();

        uint32_t sA   = sb + s * STAGE_B + 0 * TILE_B;
        uint32_t sWhi = sb + s * STAGE_B + 1 * TILE_B;
        uint32_t sWlo = sb + s * STAGE_B + 2 * TILE_B;

        #pragma unroll
        for (int ks = 0; ks < 2; ks++) {
            // B fragments for this k-step
            uint32_t whi[4][2], wlo[4][2];
            #pragma unroll
            for (int np = 0; np < 2; np++) {
                int brow = wn * 32 + np * 16 + b_row;
                uint32_t off = sw_off(brow, ks * 2 + b_c);
                uint32_t r[4];
                ldm_x4(sWhi + off, r);
                whi[np*2][0] = r[0]; whi[np*2][1] = r[1];
                whi[np*2+1][0] = r[2]; whi[np*2+1][1] = r[3];
                ldm_x4(sWlo + off, r);
                wlo[np*2][0] = r[0]; wlo[np*2][1] = r[1];
                wlo[np*2+1][0] = r[2]; wlo[np*2+1][1] = r[3];
            }
            // A fragment per mt; two independent nt-passes (dep distance 4)
            #pragma unroll
            for (int mt = 0; mt < 4; mt++) {
                int arow = wm * 64 + mt * 16 + a_row;
                uint32_t off = sw_off(arow, ks * 2 + a_c);
                uint32_t a[4];
                ldm_x4(sA + off, a);
                #pragma unroll
                for (int nt = 0; nt < 4; nt++) hmma(acc[mt][nt], a, whi[nt]);
                #pragma unroll
                for (int nt = 0; nt < 4; nt++) hmma(acc[mt][nt], a, wlo[nt]);
            }
        }
        // prefetch 3 chunks ahead into the stage freed by this iteration
        if (ci + 3 < nch) prefetch((s + 3) & 3, ci + 3);
        CP_COMMIT();
        s = (s + 1) & 3;
    }

    // epilogue
    #pragma unroll
    for (int mt = 0; mt < 4; mt++) {
        int r = m0 + wm * 64 + mt * 16 + (lane >> 2);
        #pragma unroll
        for (int nt = 0; nt < 4; nt++) {
            int c = n0 + wn * 32 + nt * 8 + (lane & 3) * 2;
            if (OUT_HALF) {
                __half* C = (__half*)Cv;
                *(__half2*)(C + (size_t)r * N + c) =
                    __floats2half2_rn(acc[mt][nt][0], acc[mt][nt][1]);
                *(__half2*)(C + (size_t)(r + 8) * N + c) =
                    __floats2half2_rn(acc[mt][nt][2], acc[mt][nt][3]);
            } else {
                float* C = (float*)Cv;
                *(float2*)(C + (size_t)r * N + c)       = make_float2(acc[mt][nt][0], acc[mt][nt][1]);
                *(float2*)(C + (size_t)(r + 8) * N + c) = make_float2(acc[mt][nt][2], acc[mt][nt][3]);
            }
        }
    }
}

// ---------------- chunked complex scan over L (Bu in fp16) -------------------
__global__ void scan_phaseA() {
    int idx = blockIdx.x * blockDim.x + threadIdx.x;
    int p = idx & (PP - 1);
    int c = (idx >> 9) & (NCHUNK - 1);
    int b = idx >> 14;
    float2 lam = d_Lam[p];
    float xr = 0.f, xi = 0.f;
    size_t base = ((size_t)b * LL + (size_t)c * CLEN) * N1;
    const __half* Xr = d_Bu + base + p;
    const __half* Xi = d_Bu + base + PP + p;
    #pragma unroll 4
    for (int j = 0; j < CLEN; j++) {
        float br = __half2float(Xr[(size_t)j * N1]);
        float bi = __half2float(Xi[(size_t)j * N1]);
        float nr = fmaf(lam.x, xr, fmaf(-lam.y, xi, br));
        float ni = fmaf(lam.x, xi, fmaf( lam.y, xr, bi));
        xr = nr; xi = ni;
    }
    d_yend[(b * NCHUNK + c) * PP + p] = make_float2(xr, xi);
}

__global__ void scan_phaseB() {
    int idx = blockIdx.x * blockDim.x + threadIdx.x;
    int p = idx & (PP - 1);
    int b = idx >> 9;
    float2 pw = d_LamPow[p];
    float cr = 0.f, ci = 0.f;
    #pragma unroll
    for (int c = 0; c < NCHUNK; c++) {
        d_cin[(b * NCHUNK + c) * PP + p] = make_float2(cr, ci);
        float2 ye = d_yend[(b * NCHUNK + c) * PP + p];
        float nr = fmaf(pw.x, cr, fmaf(-pw.y, ci, ye.x));
        float ni = fmaf(pw.x, ci, fmaf( pw.y, cr, ye.y));
        cr = nr; ci = ni;
    }
}

// phaseC: apply carry-in, emit xs rounded to fp16 for GEMM2
__global__ void scan_phaseC() {
    int idx = blockIdx.x * blockDim.x + threadIdx.x;
    int p = idx & (PP - 1);
    int c = (idx >> 9) & (NCHUNK - 1);
    int b = idx >> 14;
    float2 lam = d_Lam[p];
    float2 c0 = d_cin[(b * NCHUNK + c) * PP + p];
    float xr = c0.x, xi = c0.y;
    size_t mrow = (size_t)b * LL + (size_t)c * CLEN;
    const __half* Xr = d_Bu + mrow * N1 + p;
    const __half* Xi = d_Bu + mrow * N1 + PP + p;
    __half* Hr = d_Xh + mrow * K2 + p;
    __half* Hi = d_Xh + mrow * K2 + PP + p;
    #pragma unroll 4
    for (int j = 0; j < CLEN; j++) {
        float br = __half2float(Xr[(size_t)j * N1]);
        float bi = __half2float(Xi[(size_t)j * N1]);
        float nr = fmaf(lam.x, xr, fmaf(-lam.y, xi, br));
        float ni = fmaf(lam.x, xi, fmaf( lam.y, xr, bi));
        xr = nr; xi = ni;
        Hr[(size_t)j * K2] = __float2half(xr);
        Hi[(size_t)j * K2] = __float2half(xi);
    }
}

// ---------------- launch -----------------------------------------------------
extern "C" void kernel_launch(void* const* d_in, const int* in_sizes, int n_in,
                              void* d_out, int out_size) {
    const float* Lre      = (const float*)d_in[0];
    const float* Lim      = (const float*)d_in[1];
    const float* Bre      = (const float*)d_in[2];
    const float* Bim      = (const float*)d_in[3];
    const float* Cre      = (const float*)d_in[4];
    const float* Cim      = (const float*)d_in[5];
    const float* log_step = (const float*)d_in[6];
    const float* u        = (const float*)d_in[7];
    float* out = (float*)d_out;

    __half *Bu, *Uh, *Xh, *W1h, *W1l, *W2h, *W2l;
    cudaGetSymbolAddress((void**)&Bu,  d_Bu);
    cudaGetSymbolAddress((void**)&Uh,  d_Uh);
    cudaGetSymbolAddress((void**)&Xh,  d_Xh);
    cudaGetSymbolAddress((void**)&W1h, d_W1hi);
    cudaGetSymbolAddress((void**)&W1l, d_W1lo);
    cudaGetSymbolAddress((void**)&W2h, d_W2hi);
    cudaGetSymbolAddress((void**)&W2l, d_W2lo);

    cudaFuncSetAttribute(hmma_gemm<1>, cudaFuncAttributeMaxDynamicSharedMemorySize, GSMEM);
    cudaFuncSetAttribute(hmma_gemm<0>, cudaFuncAttributeMaxDynamicSharedMemorySize, GSMEM);

    setup_kernel<<<PP, 256>>>(Lre, Lim, Bre, Bim, log_step);
    w2_kernel<<<(HH * PP) / 256, 256>>>(Cre, Cim);
    uconv_kernel<<<(int)(((size_t)MM * K1) / 256), 256>>>(u);

    // GEMM1: Bu(re|im) = u @ W1^T -> d_Bu fp16 (M x 1024)
    hmma_gemm<1><<<dim3(N1 / 128, MM / 128), 256, GSMEM>>>(Uh, W1h, W1l, Bu, N1, K1);

    // chunked complex scan; phaseC emits fp16 xs
    scan_phaseA<<<(BB * NCHUNK * PP) / 256, 256>>>();
    scan_phaseB<<<(BB * PP) / 256, 256>>>();
    scan_phaseC<<<(BB * NCHUNK * PP) / 256, 256>>>();

    // GEMM2: ys = xs @ W2^T -> out fp32 (M x 512)
    hmma_gemm<0><<<dim3(N2 / 128, MM / 128), 256, GSMEM>>>(Xh, W2h, W2l, out, N2, K2);
}

// round 9
// speedup vs baseline: 4.9673x; 1.3153x over previous
#include <cuda_runtime.h>
#include <cuda_fp16.h>
#include <math.h>
#include <stdint.h>

// Problem constants
#define BB    8
#define LL    4096
#define HH    512
#define PP    512
#define MM    (BB*LL)     // 32768 tokens
#define N1    (2*PP)      // 1024  (Bu_re | Bu_im)
#define K1    HH          // 512
#define N2    HH          // 512
#define K2    (2*PP)      // 1024  (x_re | x_im)
#define NCHUNK 32
#define CLEN   128        // LL / NCHUNK

// ---------------- static device scratch -------------------------------------
__device__ __half  d_Bu [(size_t)MM * N1];   // Bu fp16 (64MB)
__device__ __half  d_Uh [(size_t)MM * K1];   // u rounded to fp16 (32MB)
__device__ __half  d_Xh [(size_t)MM * K2];   // xs rounded to fp16 (64MB)
__device__ __half  d_W1 [N1 * K1];           // B_bar folded, fp16
__device__ __half  d_W2 [N2 * K2];           // [2C_re | -2C_im], fp16
__device__ float2 d_Lam[PP];
__device__ float2 d_LamPow[PP];
__device__ float2 d_yend[BB * NCHUNK * PP];
__device__ float2 d_cin [BB * NCHUNK * PP];

// ---------------- helpers ----------------------------------------------------
__device__ __forceinline__ uint32_t smem_u32(const void* p) {
    uint32_t a;
    asm("{ .reg .u64 t; cvta.to.shared.u64 t, %1; cvt.u32.u64 %0, t; }" : "=r"(a) : "l"(p));
    return a;
}
__device__ __forceinline__ void cp16(uint32_t saddr, const void* g) {
    asm volatile("cp.async.cg.shared.global [%0], [%1], 16;" :: "r"(saddr), "l"(g));
}
#define CP_COMMIT() asm volatile("cp.async.commit_group;" ::: "memory")
#define CP_WAIT(n)  asm volatile("cp.async.wait_group %0;" :: "n"(n) : "memory")

__device__ __forceinline__ void ldm_x4(uint32_t addr, uint32_t* r) {
    asm volatile("ldmatrix.sync.aligned.m8n8.x4.shared.b16 {%0,%1,%2,%3}, [%4];"
                 : "=r"(r[0]), "=r"(r[1]), "=r"(r[2]), "=r"(r[3]) : "r"(addr));
}
__device__ __forceinline__ void hmma(float* c, const uint32_t* a, const uint32_t* b) {
    asm volatile(
        "mma.sync.aligned.m16n8k16.row.col.f32.f16.f16.f32 "
        "{%0,%1,%2,%3}, {%4,%5,%6,%7}, {%8,%9}, {%0,%1,%2,%3};"
        : "+f"(c[0]), "+f"(c[1]), "+f"(c[2]), "+f"(c[3])
        : "r"(a[0]), "r"(a[1]), "r"(a[2]), "r"(a[3]), "r"(b[0]), "r"(b[1]));
}

// XOR swizzle inside a 128-row x 64B tile: (row, c16) -> byte offset
__device__ __forceinline__ uint32_t sw_off(int row, int c16) {
    return (uint32_t)(row * 64 + ((c16 ^ ((row >> 1) & 3)) << 4));
}

// ---------------- setup: discretize in fp64, build W1 ------------------------
__global__ void setup_kernel(const float* __restrict__ Lre, const float* __restrict__ Lim,
                             const float* __restrict__ Bre, const float* __restrict__ Bim,
                             const float* __restrict__ log_step) {
    int p = blockIdx.x;
    __shared__ float2 s_f;
    if (threadIdx.x == 0) {
        double lr = (double)Lre[p], li = (double)Lim[p];
        double dt = exp((double)log_step[p]);
        double mag = exp(lr * dt);
        double lam_r = mag * cos(li * dt);
        double lam_i = mag * sin(li * dt);
        d_Lam[p] = make_float2((float)lam_r, (float)lam_i);
        double nr = lam_r - 1.0, ni = lam_i;
        double den = lr * lr + li * li;
        s_f = make_float2((float)((nr * lr + ni * li) / den),
                          (float)((ni * lr - nr * li) / den));
        double pr = lam_r, pi = lam_i;
        #pragma unroll
        for (int i = 0; i < 7; i++) { double r2 = pr*pr - pi*pi, i2 = 2.0*pr*pi; pr = r2; pi = i2; }
        d_LamPow[p] = make_float2((float)pr, (float)pi);
    }
    __syncthreads();
    float fr = s_f.x, fi = s_f.y;
    for (int h = threadIdx.x; h < HH; h += blockDim.x) {
        float br = Bre[p * HH + h], bi = Bim[p * HH + h];
        d_W1[p * K1 + h]        = __float2half(fr * br - fi * bi);   // Re(B_bar)
        d_W1[(PP + p) * K1 + h] = __float2half(fr * bi + fi * br);   // Im(B_bar)
    }
}

__global__ void w2_kernel(const float* __restrict__ Cre, const float* __restrict__ Cim) {
    int idx = blockIdx.x * blockDim.x + threadIdx.x;
    int h = idx >> 9, p = idx & (PP - 1);
    d_W2[h * K2 + p]      = __float2half( 2.0f * Cre[h * PP + p]);
    d_W2[h * K2 + PP + p] = __float2half(-2.0f * Cim[h * PP + p]);
}

__global__ void uconv_kernel(const float* __restrict__ u) {
    size_t i = (size_t)blockIdx.x * blockDim.x + threadIdx.x;
    d_Uh[i] = __float2half(u[i]);
}

// ---------------- HMMA fp16 GEMM: C[m,n] = sum_k A[m,k]*W[n,k] ---------------
// 128x128 CTA tile, BK=32, 8 warps of 64x32.
// 4-stage cp.async pipeline, XOR-swizzled 64B-row tiles, 1 barrier/chunk.
// OUT_HALF: write C as fp16 (GEMM1) or fp32 (GEMM2).
#define TILE_B  (128 * 64)               // 8192 B
#define STAGE_B (2 * TILE_B)             // A, W = 16384 B
#define NSTAGE  4
#define GSMEM   (NSTAGE * STAGE_B)       // 65536 B

template <int OUT_HALF>
__global__ void __launch_bounds__(256, 2)
hmma_gemm(const __half* __restrict__ A, const __half* __restrict__ W,
          void* __restrict__ Cv, int N, int K) {
    extern __shared__ char smem[];
    const uint32_t sb = smem_u32(smem);
    const int tid = threadIdx.x;
    const int wid = tid >> 5, lane = tid & 31;
    const int wm = wid >> 2, wn = wid & 3;       // warp tile: rows wm*64, cols wn*32
    const int m0 = blockIdx.y * 128, n0 = blockIdx.x * 128;

    const char* srcs[2] = {
        (const char*)(A + (size_t)m0 * K),
        (const char*)(W + (size_t)n0 * K) };
    const size_t rstride = (size_t)K * 2;

    auto prefetch = [&](int stage, int ci) {
        #pragma unroll
        for (int it = 0; it < 4; it++) {
            int id = it * 256 + tid;            // 0..1023
            int t = id >> 9;                    // tile 0..1
            int w = id & 511;
            int row = w >> 2, c = w & 3;
            cp16(sb + stage * STAGE_B + t * TILE_B + sw_off(row, c),
                 srcs[t] + (size_t)ci * 64 + (size_t)row * rstride + c * 16);
        }
    };

    float acc[4][4][4];
    #pragma unroll
    for (int i = 0; i < 4; i++)
        #pragma unroll
        for (int j = 0; j < 4; j++)
            #pragma unroll
            for (int q = 0; q < 4; q++) acc[i][j][q] = 0.f;

    const int nch = K / 32;
    prefetch(0, 0); CP_COMMIT();
    prefetch(1, 1); CP_COMMIT();
    prefetch(2, 2); CP_COMMIT();

    // fragment address components (per lane)
    const int a_row = lane & 15;
    const int a_c   = lane >> 4;                  // +0 or +1 16B column
    const int b_row = (lane & 7) + ((lane >> 4) & 1) * 8;
    const int b_c   = (lane >> 3) & 1;

    int s = 0;
    for (int ci = 0; ci < nch; ci++) {
        CP_WAIT(2);
        __syncthreads();

        uint32_t sA = sb + s * STAGE_B + 0 * TILE_B;
        uint32_t sW = sb + s * STAGE_B + 1 * TILE_B;

        #pragma unroll
        for (int ks = 0; ks < 2; ks++) {
            // B fragments for this k-step
            uint32_t bw[4][2];
            #pragma unroll
            for (int np = 0; np < 2; np++) {
                int brow = wn * 32 + np * 16 + b_row;
                uint32_t off = sw_off(brow, ks * 2 + b_c);
                uint32_t r[4];
                ldm_x4(sW + off, r);
                bw[np*2][0] = r[0]; bw[np*2][1] = r[1];
                bw[np*2+1][0] = r[2]; bw[np*2+1][1] = r[3];
            }
            // A fragment per mt; 4 independent HMMAs per mt
            #pragma unroll
            for (int mt = 0; mt < 4; mt++) {
                int arow = wm * 64 + mt * 16 + a_row;
                uint32_t off = sw_off(arow, ks * 2 + a_c);
                uint32_t a[4];
                ldm_x4(sA + off, a);
                #pragma unroll
                for (int nt = 0; nt < 4; nt++) hmma(acc[mt][nt], a, bw[nt]);
            }
        }
        // prefetch 3 chunks ahead into the stage freed by this iteration
        if (ci + 3 < nch) prefetch((s + 3) & 3, ci + 3);
        CP_COMMIT();
        s = (s + 1) & 3;
    }

    // epilogue
    #pragma unroll
    for (int mt = 0; mt < 4; mt++) {
        int r = m0 + wm * 64 + mt * 16 + (lane >> 2);
        #pragma unroll
        for (int nt = 0; nt < 4; nt++) {
            int c = n0 + wn * 32 + nt * 8 + (lane & 3) * 2;
            if (OUT_HALF) {
                __half* C = (__half*)Cv;
                *(__half2*)(C + (size_t)r * N + c) =
                    __floats2half2_rn(acc[mt][nt][0], acc[mt][nt][1]);
                *(__half2*)(C + (size_t)(r + 8) * N + c) =
                    __floats2half2_rn(acc[mt][nt][2], acc[mt][nt][3]);
            } else {
                float* C = (float*)Cv;
                *(float2*)(C + (size_t)r * N + c)       = make_float2(acc[mt][nt][0], acc[mt][nt][1]);
                *(float2*)(C + (size_t)(r + 8) * N + c) = make_float2(acc[mt][nt][2], acc[mt][nt][3]);
            }
        }
    }
}

// ---------------- chunked complex scan over L (Bu in fp16) -------------------
__global__ void scan_phaseA() {
    int idx = blockIdx.x * blockDim.x + threadIdx.x;
    int p = idx & (PP - 1);
    int c = (idx >> 9) & (NCHUNK - 1);
    int b = idx >> 14;
    float2 lam = d_Lam[p];
    float xr = 0.f, xi = 0.f;
    size_t base = ((size_t)b * LL + (size_t)c * CLEN) * N1;
    const __half* Xr = d_Bu + base + p;
    const __half* Xi = d_Bu + base + PP + p;
    #pragma unroll 4
    for (int j = 0; j < CLEN; j++) {
        float br = __half2float(Xr[(size_t)j * N1]);
        float bi = __half2float(Xi[(size_t)j * N1]);
        float nr = fmaf(lam.x, xr, fmaf(-lam.y, xi, br));
        float ni = fmaf(lam.x, xi, fmaf( lam.y, xr, bi));
        xr = nr; xi = ni;
    }
    d_yend[(b * NCHUNK + c) * PP + p] = make_float2(xr, xi);
}

__global__ void scan_phaseB() {
    int idx = blockIdx.x * blockDim.x + threadIdx.x;
    int p = idx & (PP - 1);
    int b = idx >> 9;
    float2 pw = d_LamPow[p];
    float cr = 0.f, ci = 0.f;
    #pragma unroll
    for (int c = 0; c < NCHUNK; c++) {
        d_cin[(b * NCHUNK + c) * PP + p] = make_float2(cr, ci);
        float2 ye = d_yend[(b * NCHUNK + c) * PP + p];
        float nr = fmaf(pw.x, cr, fmaf(-pw.y, ci, ye.x));
        float ni = fmaf(pw.x, ci, fmaf( pw.y, cr, ye.y));
        cr = nr; ci = ni;
    }
}

// phaseC: apply carry-in, emit xs rounded to fp16 for GEMM2
__global__ void scan_phaseC() {
    int idx = blockIdx.x * blockDim.x + threadIdx.x;
    int p = idx & (PP - 1);
    int c = (idx >> 9) & (NCHUNK - 1);
    int b = idx >> 14;
    float2 lam = d_Lam[p];
    float2 c0 = d_cin[(b * NCHUNK + c) * PP + p];
    float xr = c0.x, xi = c0.y;
    size_t mrow = (size_t)b * LL + (size_t)c * CLEN;
    const __half* Xr = d_Bu + mrow * N1 + p;
    const __half* Xi = d_Bu + mrow * N1 + PP + p;
    __half* Hr = d_Xh + mrow * K2 + p;
    __half* Hi = d_Xh + mrow * K2 + PP + p;
    #pragma unroll 4
    for (int j = 0; j < CLEN; j++) {
        float br = __half2float(Xr[(size_t)j * N1]);
        float bi = __half2float(Xi[(size_t)j * N1]);
        float nr = fmaf(lam.x, xr, fmaf(-lam.y, xi, br));
        float ni = fmaf(lam.x, xi, fmaf( lam.y, xr, bi));
        xr = nr; xi = ni;
        Hr[(size_t)j * K2] = __float2half(xr);
        Hi[(size_t)j * K2] = __float2half(xi);
    }
}

// ---------------- launch -----------------------------------------------------
extern "C" void kernel_launch(void* const* d_in, const int* in_sizes, int n_in,
                              void* d_out, int out_size) {
    const float* Lre      = (const float*)d_in[0];
    const float* Lim      = (const float*)d_in[1];
    const float* Bre      = (const float*)d_in[2];
    const float* Bim      = (const float*)d_in[3];
    const float* Cre      = (const float*)d_in[4];
    const float* Cim      = (const float*)d_in[5];
    const float* log_step = (const float*)d_in[6];
    const float* u        = (const float*)d_in[7];
    float* out = (float*)d_out;

    __half *Bu, *Uh, *Xh, *W1p, *W2p;
    cudaGetSymbolAddress((void**)&Bu,  d_Bu);
    cudaGetSymbolAddress((void**)&Uh,  d_Uh);
    cudaGetSymbolAddress((void**)&Xh,  d_Xh);
    cudaGetSymbolAddress((void**)&W1p, d_W1);
    cudaGetSymbolAddress((void**)&W2p, d_W2);

    cudaFuncSetAttribute(hmma_gemm<1>, cudaFuncAttributeMaxDynamicSharedMemorySize, GSMEM);
    cudaFuncSetAttribute(hmma_gemm<0>, cudaFuncAttributeMaxDynamicSharedMemorySize, GSMEM);

    setup_kernel<<<PP, 256>>>(Lre, Lim, Bre, Bim, log_step);
    w2_kernel<<<(HH * PP) / 256, 256>>>(Cre, Cim);
    uconv_kernel<<<(int)(((size_t)MM * K1) / 256), 256>>>(u);

    // GEMM1: Bu(re|im) = u @ W1^T -> d_Bu fp16 (M x 1024)
    hmma_gemm<1><<<dim3(N1 / 128, MM / 128), 256, GSMEM>>>(Uh, W1p, Bu, N1, K1);

    // chunked complex scan; phaseC emits fp16 xs
    scan_phaseA<<<(BB * NCHUNK * PP) / 256, 256>>>();
    scan_phaseB<<<(BB * PP) / 256, 256>>>();
    scan_phaseC<<<(BB * NCHUNK * PP) / 256, 256>>>();

    // GEMM2: ys = xs @ W2^T -> out fp32 (M x 512)
    hmma_gemm<0><<<dim3(N2 / 128, MM / 128), 256, GSMEM>>>(Xh, W2p, out, N2, K2);
}

// round 10
// speedup vs baseline: 5.1283x; 1.0324x over previous
#include <cuda_runtime.h>
#include <cuda_fp16.h>
#include <math.h>
#include <stdint.h>

// Problem constants
#define BB    8
#define LL    4096
#define HH    512
#define PP    512
#define MM    (BB*LL)     // 32768 tokens
#define N1    (2*PP)      // 1024  (Bu_re | Bu_im)
#define K1    HH          // 512
#define N2    HH          // 512
#define K2    (2*PP)      // 1024  (x_re | x_im)
#define NCHUNK 32
#define CLEN   128        // LL / NCHUNK

// ---------------- static device scratch -------------------------------------
__device__ __half  d_Bu [(size_t)MM * N1];   // Bu fp16 (64MB)
__device__ __half  d_Uh [(size_t)MM * K1];   // u rounded to fp16 (32MB)
__device__ __half  d_Xh [(size_t)MM * K2];   // xs rounded to fp16 (64MB)
__device__ __half  d_W1 [N1 * K1];           // B_bar folded, fp16
__device__ __half  d_W2 [N2 * K2];           // [2C_re | -2C_im], fp16
__device__ float2 d_Lam[PP];
__device__ float2 d_LamPow[PP];
__device__ float2 d_yend[BB * NCHUNK * PP];
__device__ float2 d_cin [BB * NCHUNK * PP];

// ---------------- helpers ----------------------------------------------------
__device__ __forceinline__ uint32_t smem_u32(const void* p) {
    uint32_t a;
    asm("{ .reg .u64 t; cvta.to.shared.u64 t, %1; cvt.u32.u64 %0, t; }" : "=r"(a) : "l"(p));
    return a;
}
__device__ __forceinline__ void cp16(uint32_t saddr, const void* g) {
    asm volatile("cp.async.cg.shared.global [%0], [%1], 16;" :: "r"(saddr), "l"(g));
}
#define CP_COMMIT() asm volatile("cp.async.commit_group;" ::: "memory")
#define CP_WAIT(n)  asm volatile("cp.async.wait_group %0;" :: "n"(n) : "memory")

__device__ __forceinline__ void ldm_x4(uint32_t addr, uint32_t* r) {
    asm volatile("ldmatrix.sync.aligned.m8n8.x4.shared.b16 {%0,%1,%2,%3}, [%4];"
                 : "=r"(r[0]), "=r"(r[1]), "=r"(r[2]), "=r"(r[3]) : "r"(addr));
}
__device__ __forceinline__ void hmma(float* c, const uint32_t* a, const uint32_t* b) {
    asm volatile(
        "mma.sync.aligned.m16n8k16.row.col.f32.f16.f16.f32 "
        "{%0,%1,%2,%3}, {%4,%5,%6,%7}, {%8,%9}, {%0,%1,%2,%3};"
        : "+f"(c[0]), "+f"(c[1]), "+f"(c[2]), "+f"(c[3])
        : "r"(a[0]), "r"(a[1]), "r"(a[2]), "r"(a[3]), "r"(b[0]), "r"(b[1]));
}

// XOR swizzle inside a 128-row x 64B tile: (row, c16) -> byte offset
__device__ __forceinline__ uint32_t sw_off(int row, int c16) {
    return (uint32_t)(row * 64 + ((c16 ^ ((row >> 1) & 3)) << 4));
}

// ---------------- setup: discretize in fp64, build W1 ------------------------
__global__ void setup_kernel(const float* __restrict__ Lre, const float* __restrict__ Lim,
                             const float* __restrict__ Bre, const float* __restrict__ Bim,
                             const float* __restrict__ log_step) {
    int p = blockIdx.x;
    __shared__ float2 s_f;
    if (threadIdx.x == 0) {
        double lr = (double)Lre[p], li = (double)Lim[p];
        double dt = exp((double)log_step[p]);
        double mag = exp(lr * dt);
        double lam_r = mag * cos(li * dt);
        double lam_i = mag * sin(li * dt);
        d_Lam[p] = make_float2((float)lam_r, (float)lam_i);
        double nr = lam_r - 1.0, ni = lam_i;
        double den = lr * lr + li * li;
        s_f = make_float2((float)((nr * lr + ni * li) / den),
                          (float)((ni * lr - nr * li) / den));
        double pr = lam_r, pi = lam_i;
        #pragma unroll
        for (int i = 0; i < 7; i++) { double r2 = pr*pr - pi*pi, i2 = 2.0*pr*pi; pr = r2; pi = i2; }
        d_LamPow[p] = make_float2((float)pr, (float)pi);
    }
    __syncthreads();
    float fr = s_f.x, fi = s_f.y;
    for (int h = threadIdx.x; h < HH; h += blockDim.x) {
        float br = Bre[p * HH + h], bi = Bim[p * HH + h];
        d_W1[p * K1 + h]        = __float2half(fr * br - fi * bi);   // Re(B_bar)
        d_W1[(PP + p) * K1 + h] = __float2half(fr * bi + fi * br);   // Im(B_bar)
    }
}

__global__ void w2_kernel(const float* __restrict__ Cre, const float* __restrict__ Cim) {
    int idx = blockIdx.x * blockDim.x + threadIdx.x;
    int h = idx >> 9, p = idx & (PP - 1);
    d_W2[h * K2 + p]      = __float2half( 2.0f * Cre[h * PP + p]);
    d_W2[h * K2 + PP + p] = __float2half(-2.0f * Cim[h * PP + p]);
}

__global__ void uconv_kernel(const float* __restrict__ u) {
    size_t i = (size_t)blockIdx.x * blockDim.x + threadIdx.x;
    d_Uh[i] = __float2half(u[i]);
}

// ---------------- HMMA fp16 GEMM: C[m,n] = sum_k A[m,k]*W[n,k] ---------------
// 128x128 CTA tile, BK=32, 4 warps of 64x64 (128 threads).
// 4-stage cp.async pipeline, XOR-swizzled 64B-row tiles, 1 barrier/chunk.
// OUT_HALF: write C as fp16 (GEMM1) or fp32 (GEMM2).
#define TILE_B  (128 * 64)               // 8192 B
#define STAGE_B (2 * TILE_B)             // A, W = 16384 B
#define NSTAGE  4
#define GSMEM   (NSTAGE * STAGE_B)       // 65536 B

template <int OUT_HALF>
__global__ void __launch_bounds__(128, 2)
hmma_gemm(const __half* __restrict__ A, const __half* __restrict__ W,
          void* __restrict__ Cv, int N, int K) {
    extern __shared__ char smem[];
    const uint32_t sb = smem_u32(smem);
    const int tid = threadIdx.x;
    const int wid = tid >> 5, lane = tid & 31;
    const int wm = wid >> 1, wn = wid & 1;       // warp tile: rows wm*64, cols wn*64
    const int m0 = blockIdx.y * 128, n0 = blockIdx.x * 128;

    const char* srcs[2] = {
        (const char*)(A + (size_t)m0 * K),
        (const char*)(W + (size_t)n0 * K) };
    const size_t rstride = (size_t)K * 2;

    auto prefetch = [&](int stage, int ci) {
        #pragma unroll
        for (int it = 0; it < 8; it++) {
            int id = it * 128 + tid;            // 0..1023
            int t = id >> 9;                    // tile 0..1
            int w = id & 511;
            int row = w >> 2, c = w & 3;
            cp16(sb + stage * STAGE_B + t * TILE_B + sw_off(row, c),
                 srcs[t] + (size_t)ci * 64 + (size_t)row * rstride + c * 16);
        }
    };

    float acc[4][8][4];
    #pragma unroll
    for (int i = 0; i < 4; i++)
        #pragma unroll
        for (int j = 0; j < 8; j++)
            #pragma unroll
            for (int q = 0; q < 4; q++) acc[i][j][q] = 0.f;

    const int nch = K / 32;
    prefetch(0, 0); CP_COMMIT();
    prefetch(1, 1); CP_COMMIT();
    prefetch(2, 2); CP_COMMIT();

    // fragment address components (per lane)
    const int a_row = lane & 15;
    const int a_c   = lane >> 4;                  // +0 or +1 16B column
    const int b_row = (lane & 7) + ((lane >> 4) & 1) * 8;
    const int b_c   = (lane >> 3) & 1;

    int s = 0;
    for (int ci = 0; ci < nch; ci++) {
        CP_WAIT(2);
        __syncthreads();

        uint32_t sA = sb + s * STAGE_B + 0 * TILE_B;
        uint32_t sW = sb + s * STAGE_B + 1 * TILE_B;

        #pragma unroll
        for (int ks = 0; ks < 2; ks++) {
            // B fragments: 64 cols -> 4 ldmatrix.x4 -> 8 n8 fragments
            uint32_t bw[8][2];
            #pragma unroll
            for (int np = 0; np < 4; np++) {
                int brow = wn * 64 + np * 16 + b_row;
                uint32_t off = sw_off(brow, ks * 2 + b_c);
                uint32_t r[4];
                ldm_x4(sW + off, r);
                bw[np*2][0] = r[0]; bw[np*2][1] = r[1];
                bw[np*2+1][0] = r[2]; bw[np*2+1][1] = r[3];
            }
            // A fragment per mt; 8 independent HMMAs per mt
            #pragma unroll
            for (int mt = 0; mt < 4; mt++) {
                int arow = wm * 64 + mt * 16 + a_row;
                uint32_t off = sw_off(arow, ks * 2 + a_c);
                uint32_t a[4];
                ldm_x4(sA + off, a);
                #pragma unroll
                for (int nt = 0; nt < 8; nt++) hmma(acc[mt][nt], a, bw[nt]);
            }
        }
        // prefetch 3 chunks ahead into the stage freed by this iteration
        if (ci + 3 < nch) prefetch((s + 3) & 3, ci + 3);
        CP_COMMIT();
        s = (s + 1) & 3;
    }

    // epilogue
    #pragma unroll
    for (int mt = 0; mt < 4; mt++) {
        int r = m0 + wm * 64 + mt * 16 + (lane >> 2);
        #pragma unroll
        for (int nt = 0; nt < 8; nt++) {
            int c = n0 + wn * 64 + nt * 8 + (lane & 3) * 2;
            if (OUT_HALF) {
                __half* C = (__half*)Cv;
                *(__half2*)(C + (size_t)r * N + c) =
                    __floats2half2_rn(acc[mt][nt][0], acc[mt][nt][1]);
                *(__half2*)(C + (size_t)(r + 8) * N + c) =
                    __floats2half2_rn(acc[mt][nt][2], acc[mt][nt][3]);
            } else {
                float* C = (float*)Cv;
                *(float2*)(C + (size_t)r * N + c)       = make_float2(acc[mt][nt][0], acc[mt][nt][1]);
                *(float2*)(C + (size_t)(r + 8) * N + c) = make_float2(acc[mt][nt][2], acc[mt][nt][3]);
            }
        }
    }
}

// ---------------- chunked complex scan over L (Bu in fp16) -------------------
__global__ void scan_phaseA() {
    int idx = blockIdx.x * blockDim.x + threadIdx.x;
    int p = idx & (PP - 1);
    int c = (idx >> 9) & (NCHUNK - 1);
    int b = idx >> 14;
    float2 lam = d_Lam[p];
    float xr = 0.f, xi = 0.f;
    size_t base = ((size_t)b * LL + (size_t)c * CLEN) * N1;
    const __half* Xr = d_Bu + base + p;
    const __half* Xi = d_Bu + base + PP + p;
    #pragma unroll 4
    for (int j = 0; j < CLEN; j++) {
        float br = __half2float(Xr[(size_t)j * N1]);
        float bi = __half2float(Xi[(size_t)j * N1]);
        float nr = fmaf(lam.x, xr, fmaf(-lam.y, xi, br));
        float ni = fmaf(lam.x, xi, fmaf( lam.y, xr, bi));
        xr = nr; xi = ni;
    }
    d_yend[(b * NCHUNK + c) * PP + p] = make_float2(xr, xi);
}

__global__ void scan_phaseB() {
    int idx = blockIdx.x * blockDim.x + threadIdx.x;
    int p = idx & (PP - 1);
    int b = idx >> 9;
    float2 pw = d_LamPow[p];
    float cr = 0.f, ci = 0.f;
    #pragma unroll
    for (int c = 0; c < NCHUNK; c++) {
        d_cin[(b * NCHUNK + c) * PP + p] = make_float2(cr, ci);
        float2 ye = d_yend[(b * NCHUNK + c) * PP + p];
        float nr = fmaf(pw.x, cr, fmaf(-pw.y, ci, ye.x));
        float ni = fmaf(pw.x, ci, fmaf( pw.y, cr, ye.y));
        cr = nr; ci = ni;
    }
}

// phaseC: apply carry-in, emit xs rounded to fp16 for GEMM2
__global__ void scan_phaseC() {
    int idx = blockIdx.x * blockDim.x + threadIdx.x;
    int p = idx & (PP - 1);
    int c = (idx >> 9) & (NCHUNK - 1);
    int b = idx >> 14;
    float2 lam = d_Lam[p];
    float2 c0 = d_cin[(b * NCHUNK + c) * PP + p];
    float xr = c0.x, xi = c0.y;
    size_t mrow = (size_t)b * LL + (size_t)c * CLEN;
    const __half* Xr = d_Bu + mrow * N1 + p;
    const __half* Xi = d_Bu + mrow * N1 + PP + p;
    __half* Hr = d_Xh + mrow * K2 + p;
    __half* Hi = d_Xh + mrow * K2 + PP + p;
    #pragma unroll 4
    for (int j = 0; j < CLEN; j++) {
        float br = __half2float(Xr[(size_t)j * N1]);
        float bi = __half2float(Xi[(size_t)j * N1]);
        float nr = fmaf(lam.x, xr, fmaf(-lam.y, xi, br));
        float ni = fmaf(lam.x, xi, fmaf( lam.y, xr, bi));
        xr = nr; xi = ni;
        Hr[(size_t)j * K2] = __float2half(xr);
        Hi[(size_t)j * K2] = __float2half(xi);
    }
}

// ---------------- launch -----------------------------------------------------
extern "C" void kernel_launch(void* const* d_in, const int* in_sizes, int n_in,
                              void* d_out, int out_size) {
    const float* Lre      = (const float*)d_in[0];
    const float* Lim      = (const float*)d_in[1];
    const float* Bre      = (const float*)d_in[2];
    const float* Bim      = (const float*)d_in[3];
    const float* Cre      = (const float*)d_in[4];
    const float* Cim      = (const float*)d_in[5];
    const float* log_step = (const float*)d_in[6];
    const float* u        = (const float*)d_in[7];
    float* out = (float*)d_out;

    __half *Bu, *Uh, *Xh, *W1p, *W2p;
    cudaGetSymbolAddress((void**)&Bu,  d_Bu);
    cudaGetSymbolAddress((void**)&Uh,  d_Uh);
    cudaGetSymbolAddress((void**)&Xh,  d_Xh);
    cudaGetSymbolAddress((void**)&W1p, d_W1);
    cudaGetSymbolAddress((void**)&W2p, d_W2);

    cudaFuncSetAttribute(hmma_gemm<1>, cudaFuncAttributeMaxDynamicSharedMemorySize, GSMEM);
    cudaFuncSetAttribute(hmma_gemm<0>, cudaFuncAttributeMaxDynamicSharedMemorySize, GSMEM);

    setup_kernel<<<PP, 256>>>(Lre, Lim, Bre, Bim, log_step);
    w2_kernel<<<(HH * PP) / 256, 256>>>(Cre, Cim);
    uconv_kernel<<<(int)(((size_t)MM * K1) / 256), 256>>>(u);

    // GEMM1: Bu(re|im) = u @ W1^T -> d_Bu fp16 (M x 1024)
    hmma_gemm<1><<<dim3(N1 / 128, MM / 128), 128, GSMEM>>>(Uh, W1p, Bu, N1, K1);

    // chunked complex scan; phaseC emits fp16 xs
    scan_phaseA<<<(BB * NCHUNK * PP) / 256, 256>>>();
    scan_phaseB<<<(BB * PP) / 256, 256>>>();
    scan_phaseC<<<(BB * NCHUNK * PP) / 256, 256>>>();

    // GEMM2: ys = xs @ W2^T -> out fp32 (M x 512)
    hmma_gemm<0><<<dim3(N2 / 128, MM / 128), 128, GSMEM>>>(Xh, W2p, out, N2, K2);
}

// round 11
// speedup vs baseline: 5.4963x; 1.0718x over previous
#include <cuda_runtime.h>
#include <cuda_fp16.h>
#include <math.h>
#include <stdint.h>

// Problem constants
#define BB    8
#define LL    4096
#define HH    512
#define PP    512
#define MM    (BB*LL)     // 32768 tokens
#define N1    (2*PP)      // 1024  (Bu_re | Bu_im)
#define K1    HH          // 512
#define N2    HH          // 512
#define K2    (2*PP)      // 1024  (x_re | x_im)
#define NCHUNK 32
#define CLEN   128        // LL / NCHUNK

// ---------------- static device scratch -------------------------------------
__device__ __half  d_Bu [(size_t)MM * N1];   // Bu fp16 (64MB)
__device__ __half  d_Uh [(size_t)MM * K1];   // u rounded to fp16 (32MB)
__device__ __half  d_Xh [(size_t)MM * K2];   // xs rounded to fp16 (64MB)
__device__ __half  d_W1 [N1 * K1];           // B_bar folded, fp16
__device__ __half  d_W2 [N2 * K2];           // [2C_re | -2C_im], fp16
__device__ float2 d_Lam[PP];
__device__ float2 d_LamPow[PP];
__device__ float2 d_yend[BB * NCHUNK * PP];
__device__ float2 d_cin [BB * NCHUNK * PP];

// ---------------- helpers ----------------------------------------------------
__device__ __forceinline__ uint32_t smem_u32(const void* p) {
    uint32_t a;
    asm("{ .reg .u64 t; cvta.to.shared.u64 t, %1; cvt.u32.u64 %0, t; }" : "=r"(a) : "l"(p));
    return a;
}
__device__ __forceinline__ void cp16(uint32_t saddr, const void* g) {
    asm volatile("cp.async.cg.shared.global [%0], [%1], 16;" :: "r"(saddr), "l"(g));
}
#define CP_COMMIT() asm volatile("cp.async.commit_group;" ::: "memory")
#define CP_WAIT(n)  asm volatile("cp.async.wait_group %0;" :: "n"(n) : "memory")

__device__ __forceinline__ void ldm_x4(uint32_t addr, uint32_t* r) {
    asm volatile("ldmatrix.sync.aligned.m8n8.x4.shared.b16 {%0,%1,%2,%3}, [%4];"
                 : "=r"(r[0]), "=r"(r[1]), "=r"(r[2]), "=r"(r[3]) : "r"(addr));
}
__device__ __forceinline__ void hmma(float* c, const uint32_t* a, const uint32_t* b) {
    asm volatile(
        "mma.sync.aligned.m16n8k16.row.col.f32.f16.f16.f32 "
        "{%0,%1,%2,%3}, {%4,%5,%6,%7}, {%8,%9}, {%0,%1,%2,%3};"
        : "+f"(c[0]), "+f"(c[1]), "+f"(c[2]), "+f"(c[3])
        : "r"(a[0]), "r"(a[1]), "r"(a[2]), "r"(a[3]), "r"(b[0]), "r"(b[1]));
}

// XOR swizzle inside a 128-row x 64B tile: (row, c16) -> byte offset
__device__ __forceinline__ uint32_t sw_off(int row, int c16) {
    return (uint32_t)(row * 64 + ((c16 ^ ((row >> 1) & 3)) << 4));
}

// ---------------- setup: discretize in fp64, build W1 ------------------------
__global__ void setup_kernel(const float* __restrict__ Lre, const float* __restrict__ Lim,
                             const float* __restrict__ Bre, const float* __restrict__ Bim,
                             const float* __restrict__ log_step) {
    int p = blockIdx.x;
    __shared__ float2 s_f;
    if (threadIdx.x == 0) {
        double lr = (double)Lre[p], li = (double)Lim[p];
        double dt = exp((double)log_step[p]);
        double mag = exp(lr * dt);
        double lam_r = mag * cos(li * dt);
        double lam_i = mag * sin(li * dt);
        d_Lam[p] = make_float2((float)lam_r, (float)lam_i);
        double nr = lam_r - 1.0, ni = lam_i;
        double den = lr * lr + li * li;
        s_f = make_float2((float)((nr * lr + ni * li) / den),
                          (float)((ni * lr - nr * li) / den));
        double pr = lam_r, pi = lam_i;
        #pragma unroll
        for (int i = 0; i < 7; i++) { double r2 = pr*pr - pi*pi, i2 = 2.0*pr*pi; pr = r2; pi = i2; }
        d_LamPow[p] = make_float2((float)pr, (float)pi);
    }
    __syncthreads();
    float fr = s_f.x, fi = s_f.y;
    for (int h = threadIdx.x; h < HH; h += blockDim.x) {
        float br = Bre[p * HH + h], bi = Bim[p * HH + h];
        d_W1[p * K1 + h]        = __float2half(fr * br - fi * bi);   // Re(B_bar)
        d_W1[(PP + p) * K1 + h] = __float2half(fr * bi + fi * br);   // Im(B_bar)
    }
}

__global__ void w2_kernel(const float* __restrict__ Cre, const float* __restrict__ Cim) {
    int idx = blockIdx.x * blockDim.x + threadIdx.x;
    int h = idx >> 9, p = idx & (PP - 1);
    d_W2[h * K2 + p]      = __float2half( 2.0f * Cre[h * PP + p]);
    d_W2[h * K2 + PP + p] = __float2half(-2.0f * Cim[h * PP + p]);
}

// vectorized: 8 floats -> 8 halves (one uint4 store) per thread
__global__ void uconv_kernel(const float* __restrict__ u) {
    size_t i = ((size_t)blockIdx.x * blockDim.x + threadIdx.x) * 8;
    float4 a = *(const float4*)(u + i);
    float4 b = *(const float4*)(u + i + 4);
    __half2 h0 = __floats2half2_rn(a.x, a.y);
    __half2 h1 = __floats2half2_rn(a.z, a.w);
    __half2 h2 = __floats2half2_rn(b.x, b.y);
    __half2 h3 = __floats2half2_rn(b.z, b.w);
    uint4 out;
    out.x = *(uint32_t*)&h0; out.y = *(uint32_t*)&h1;
    out.z = *(uint32_t*)&h2; out.w = *(uint32_t*)&h3;
    *(uint4*)(d_Uh + i) = out;
}

// ---------------- HMMA fp16 GEMM: C[m,n] = sum_k A[m,k]*W[n,k] ---------------
// 128x128 CTA tile, BK=32, 4 warps of 64x64 (128 threads).
// 4-stage cp.async pipeline, XOR-swizzled 64B-row tiles, 1 barrier/chunk.
// Per k-step: all 8 ldmatrix first, then 32 HMMAs. Prefetch issued at chunk top.
#define TILE_B  (128 * 64)               // 8192 B
#define STAGE_B (2 * TILE_B)             // A, W = 16384 B
#define NSTAGE  4
#define GSMEM   (NSTAGE * STAGE_B)       // 65536 B

template <int OUT_HALF>
__global__ void __launch_bounds__(128, 2)
hmma_gemm(const __half* __restrict__ A, const __half* __restrict__ W,
          void* __restrict__ Cv, int N, int K) {
    extern __shared__ char smem[];
    const uint32_t sb = smem_u32(smem);
    const int tid = threadIdx.x;
    const int wid = tid >> 5, lane = tid & 31;
    const int wm = wid >> 1, wn = wid & 1;       // warp tile: rows wm*64, cols wn*64
    const int m0 = blockIdx.y * 128, n0 = blockIdx.x * 128;

    const char* srcs[2] = {
        (const char*)(A + (size_t)m0 * K),
        (const char*)(W + (size_t)n0 * K) };
    const size_t rstride = (size_t)K * 2;

    auto prefetch = [&](int stage, int ci) {
        #pragma unroll
        for (int it = 0; it < 8; it++) {
            int id = it * 128 + tid;            // 0..1023
            int t = id >> 9;                    // tile 0..1
            int w = id & 511;
            int row = w >> 2, c = w & 3;
            cp16(sb + stage * STAGE_B + t * TILE_B + sw_off(row, c),
                 srcs[t] + (size_t)ci * 64 + (size_t)row * rstride + c * 16);
        }
    };

    float acc[4][8][4];
    #pragma unroll
    for (int i = 0; i < 4; i++)
        #pragma unroll
        for (int j = 0; j < 8; j++)
            #pragma unroll
            for (int q = 0; q < 4; q++) acc[i][j][q] = 0.f;

    const int nch = K / 32;
    prefetch(0, 0); CP_COMMIT();
    prefetch(1, 1); CP_COMMIT();
    prefetch(2, 2); CP_COMMIT();

    // fragment address components (per lane)
    const int a_row = lane & 15;
    const int a_c   = lane >> 4;                  // +0 or +1 16B column
    const int b_row = (lane & 7) + ((lane >> 4) & 1) * 8;
    const int b_c   = (lane >> 3) & 1;

    int s = 0;
    for (int ci = 0; ci < nch; ci++) {
        CP_WAIT(2);
        __syncthreads();

        // issue next prefetch FIRST so cp.async overlaps the MMA burst
        if (ci + 3 < nch) prefetch((s + 3) & 3, ci + 3);
        CP_COMMIT();

        uint32_t sA = sb + s * STAGE_B + 0 * TILE_B;
        uint32_t sW = sb + s * STAGE_B + 1 * TILE_B;

        #pragma unroll
        for (int ks = 0; ks < 2; ks++) {
            // load ALL fragments for this k-step first (8 ldmatrix cover each other)
            uint32_t bw[8][2], av[4][4];
            #pragma unroll
            for (int np = 0; np < 4; np++) {
                int brow = wn * 64 + np * 16 + b_row;
                uint32_t r[4];
                ldm_x4(sW + sw_off(brow, ks * 2 + b_c), r);
                bw[np*2][0] = r[0]; bw[np*2][1] = r[1];
                bw[np*2+1][0] = r[2]; bw[np*2+1][1] = r[3];
            }
            #pragma unroll
            for (int mt = 0; mt < 4; mt++) {
                int arow = wm * 64 + mt * 16 + a_row;
                ldm_x4(sA + sw_off(arow, ks * 2 + a_c), av[mt]);
            }
            // 32 back-to-back HMMAs, no interleaved shared ops
            #pragma unroll
            for (int mt = 0; mt < 4; mt++)
                #pragma unroll
                for (int nt = 0; nt < 8; nt++) hmma(acc[mt][nt], av[mt], bw[nt]);
        }
        s = (s + 1) & 3;
    }

    // epilogue
    #pragma unroll
    for (int mt = 0; mt < 4; mt++) {
        int r = m0 + wm * 64 + mt * 16 + (lane >> 2);
        #pragma unroll
        for (int nt = 0; nt < 8; nt++) {
            int c = n0 + wn * 64 + nt * 8 + (lane & 3) * 2;
            if (OUT_HALF) {
                __half* C = (__half*)Cv;
                *(__half2*)(C + (size_t)r * N + c) =
                    __floats2half2_rn(acc[mt][nt][0], acc[mt][nt][1]);
                *(__half2*)(C + (size_t)(r + 8) * N + c) =
                    __floats2half2_rn(acc[mt][nt][2], acc[mt][nt][3]);
            } else {
                float* C = (float*)Cv;
                *(float2*)(C + (size_t)r * N + c)       = make_float2(acc[mt][nt][0], acc[mt][nt][1]);
                *(float2*)(C + (size_t)(r + 8) * N + c) = make_float2(acc[mt][nt][2], acc[mt][nt][3]);
            }
        }
    }
}

// ---------------- chunked complex scan over L (Bu fp16, 2 p's per thread) ----
__global__ void scan_phaseA() {
    int idx = blockIdx.x * blockDim.x + threadIdx.x;   // 0..65535
    int pp = idx & 255;                  // half2 index; p0 = 2*pp
    int c  = (idx >> 8) & (NCHUNK - 1);
    int b  = idx >> 13;
    float2 lam0 = d_Lam[2 * pp], lam1 = d_Lam[2 * pp + 1];
    float xr0 = 0.f, xi0 = 0.f, xr1 = 0.f, xi1 = 0.f;
    size_t base = ((size_t)b * LL + (size_t)c * CLEN) * N1;
    const __half2* Xr = (const __half2*)(d_Bu + base) + pp;
    const __half2* Xi = (const __half2*)(d_Bu + base + PP) + pp;
    #pragma unroll 4
    for (int j = 0; j < CLEN; j++) {
        float2 br = __half22float2(Xr[(size_t)j * (N1 / 2)]);
        float2 bi = __half22float2(Xi[(size_t)j * (N1 / 2)]);
        float nr0 = fmaf(lam0.x, xr0, fmaf(-lam0.y, xi0, br.x));
        float ni0 = fmaf(lam0.x, xi0, fmaf( lam0.y, xr0, bi.x));
        float nr1 = fmaf(lam1.x, xr1, fmaf(-lam1.y, xi1, br.y));
        float ni1 = fmaf(lam1.x, xi1, fmaf( lam1.y, xr1, bi.y));
        xr0 = nr0; xi0 = ni0; xr1 = nr1; xi1 = ni1;
    }
    int yb = (b * NCHUNK + c) * PP + 2 * pp;
    d_yend[yb]     = make_float2(xr0, xi0);
    d_yend[yb + 1] = make_float2(xr1, xi1);
}

__global__ void scan_phaseB() {
    int idx = blockIdx.x * blockDim.x + threadIdx.x;
    int p = idx & (PP - 1);
    int b = idx >> 9;
    float2 pw = d_LamPow[p];
    float cr = 0.f, ci = 0.f;
    #pragma unroll
    for (int c = 0; c < NCHUNK; c++) {
        d_cin[(b * NCHUNK + c) * PP + p] = make_float2(cr, ci);
        float2 ye = d_yend[(b * NCHUNK + c) * PP + p];
        float nr = fmaf(pw.x, cr, fmaf(-pw.y, ci, ye.x));
        float ni = fmaf(pw.x, ci, fmaf( pw.y, cr, ye.y));
        cr = nr; ci = ni;
    }
}

// phaseC: apply carry-in, emit xs rounded to fp16 for GEMM2
__global__ void scan_phaseC() {
    int idx = blockIdx.x * blockDim.x + threadIdx.x;
    int pp = idx & 255;
    int c  = (idx >> 8) & (NCHUNK - 1);
    int b  = idx >> 13;
    float2 lam0 = d_Lam[2 * pp], lam1 = d_Lam[2 * pp + 1];
    int cb = (b * NCHUNK + c) * PP + 2 * pp;
    float2 c0 = d_cin[cb], c1 = d_cin[cb + 1];
    float xr0 = c0.x, xi0 = c0.y, xr1 = c1.x, xi1 = c1.y;
    size_t mrow = (size_t)b * LL + (size_t)c * CLEN;
    const __half2* Xr = (const __half2*)(d_Bu + mrow * N1) + pp;
    const __half2* Xi = (const __half2*)(d_Bu + mrow * N1 + PP) + pp;
    __half2* Hr = (__half2*)(d_Xh + mrow * K2) + pp;
    __half2* Hi = (__half2*)(d_Xh + mrow * K2 + PP) + pp;
    #pragma unroll 4
    for (int j = 0; j < CLEN; j++) {
        float2 br = __half22float2(Xr[(size_t)j * (N1 / 2)]);
        float2 bi = __half22float2(Xi[(size_t)j * (N1 / 2)]);
        float nr0 = fmaf(lam0.x, xr0, fmaf(-lam0.y, xi0, br.x));
        float ni0 = fmaf(lam0.x, xi0, fmaf( lam0.y, xr0, bi.x));
        float nr1 = fmaf(lam1.x, xr1, fmaf(-lam1.y, xi1, br.y));
        float ni1 = fmaf(lam1.x, xi1, fmaf( lam1.y, xr1, bi.y));
        xr0 = nr0; xi0 = ni0; xr1 = nr1; xi1 = ni1;
        Hr[(size_t)j * (K2 / 2)] = __floats2half2_rn(xr0, xr1);
        Hi[(size_t)j * (K2 / 2)] = __floats2half2_rn(xi0, xi1);
    }
}

// ---------------- launch -----------------------------------------------------
extern "C" void kernel_launch(void* const* d_in, const int* in_sizes, int n_in,
                              void* d_out, int out_size) {
    const float* Lre      = (const float*)d_in[0];
    const float* Lim      = (const float*)d_in[1];
    const float* Bre      = (const float*)d_in[2];
    const float* Bim      = (const float*)d_in[3];
    const float* Cre      = (const float*)d_in[4];
    const float* Cim      = (const float*)d_in[5];
    const float* log_step = (const float*)d_in[6];
    const float* u        = (const float*)d_in[7];
    float* out = (float*)d_out;

    __half *Bu, *Uh, *Xh, *W1p, *W2p;
    cudaGetSymbolAddress((void**)&Bu,  d_Bu);
    cudaGetSymbolAddress((void**)&Uh,  d_Uh);
    cudaGetSymbolAddress((void**)&Xh,  d_Xh);
    cudaGetSymbolAddress((void**)&W1p, d_W1);
    cudaGetSymbolAddress((void**)&W2p, d_W2);

    cudaFuncSetAttribute(hmma_gemm<1>, cudaFuncAttributeMaxDynamicSharedMemorySize, GSMEM);
    cudaFuncSetAttribute(hmma_gemm<0>, cudaFuncAttributeMaxDynamicSharedMemorySize, GSMEM);

    setup_kernel<<<PP, 256>>>(Lre, Lim, Bre, Bim, log_step);
    w2_kernel<<<(HH * PP) / 256, 256>>>(Cre, Cim);
    uconv_kernel<<<(int)(((size_t)MM * K1) / 8 / 256), 256>>>(u);

    // GEMM1: Bu(re|im) = u @ W1^T -> d_Bu fp16 (M x 1024)
    hmma_gemm<1><<<dim3(N1 / 128, MM / 128), 128, GSMEM>>>(Uh, W1p, Bu, N1, K1);

    // chunked complex scan; phaseC emits fp16 xs
    scan_phaseA<<<(BB * NCHUNK * PP / 2) / 256, 256>>>();
    scan_phaseB<<<(BB * PP) / 256, 256>>>();
    scan_phaseC<<<(BB * NCHUNK * PP / 2) / 256, 256>>>();

    // GEMM2: ys = xs @ W2^T -> out fp32 (M x 512)
    hmma_gemm<0><<<dim3(N2 / 128, MM / 128), 128, GSMEM>>>(Xh, W2p, out, N2, K2);
}

// round 12
// speedup vs baseline: 6.0225x; 1.0957x over previous
#include <cuda_runtime.h>
#include <cuda_fp16.h>
#include <math.h>
#include <stdint.h>

// Problem constants
#define BB    8
#define LL    4096
#define HH    512
#define PP    512
#define MM    (BB*LL)     // 32768 tokens
#define N1    (2*PP)      // 1024  (Bu_re | Bu_im)
#define K1    HH          // 512
#define N2    HH          // 512
#define K2    (2*PP)      // 1024  (x_re | x_im)
#define NCHUNK 64
#define CLEN   64         // LL / NCHUNK

// ---------------- static device scratch -------------------------------------
__device__ __half  d_Bu [(size_t)MM * N1];   // Bu fp16 (64MB)
__device__ __half  d_Uh [(size_t)MM * K1];   // u rounded to fp16 (32MB)
__device__ __half  d_Xh [(size_t)MM * K2];   // xs rounded to fp16 (64MB)
__device__ __half  d_W1 [N1 * K1];           // B_bar folded, fp16
__device__ __half  d_W2 [N2 * K2];           // [2C_re | -2C_im], fp16
__device__ float2 d_Lam[PP];
__device__ float2 d_LamPow[PP];              // lam^CLEN
__device__ float2 d_yend[BB * NCHUNK * PP];
__device__ float2 d_cin [BB * NCHUNK * PP];

// ---------------- helpers ----------------------------------------------------
__device__ __forceinline__ uint32_t smem_u32(const void* p) {
    uint32_t a;
    asm("{ .reg .u64 t; cvta.to.shared.u64 t, %1; cvt.u32.u64 %0, t; }" : "=r"(a) : "l"(p));
    return a;
}
__device__ __forceinline__ void cp16(uint32_t saddr, const void* g) {
    asm volatile("cp.async.cg.shared.global [%0], [%1], 16;" :: "r"(saddr), "l"(g));
}
#define CP_COMMIT() asm volatile("cp.async.commit_group;" ::: "memory")
#define CP_WAIT(n)  asm volatile("cp.async.wait_group %0;" :: "n"(n) : "memory")

__device__ __forceinline__ void ldm_x4(uint32_t addr, uint32_t* r) {
    asm volatile("ldmatrix.sync.aligned.m8n8.x4.shared.b16 {%0,%1,%2,%3}, [%4];"
                 : "=r"(r[0]), "=r"(r[1]), "=r"(r[2]), "=r"(r[3]) : "r"(addr));
}
__device__ __forceinline__ void hmma(float* c, const uint32_t* a, const uint32_t* b) {
    asm volatile(
        "mma.sync.aligned.m16n8k16.row.col.f32.f16.f16.f32 "
        "{%0,%1,%2,%3}, {%4,%5,%6,%7}, {%8,%9}, {%0,%1,%2,%3};"
        : "+f"(c[0]), "+f"(c[1]), "+f"(c[2]), "+f"(c[3])
        : "r"(a[0]), "r"(a[1]), "r"(a[2]), "r"(a[3]), "r"(b[0]), "r"(b[1]));
}

// Full XOR swizzle inside a 128-row x 128B tile: (row, c16 in 0..7) -> byte offset
__device__ __forceinline__ uint32_t sw_off(int row, int c16) {
    return (uint32_t)(row * 128 + ((c16 ^ (row & 7)) << 4));
}

// ---------------- setup: discretize in fp64, build W1 ------------------------
__global__ void setup_kernel(const float* __restrict__ Lre, const float* __restrict__ Lim,
                             const float* __restrict__ Bre, const float* __restrict__ Bim,
                             const float* __restrict__ log_step) {
    int p = blockIdx.x;
    __shared__ float2 s_f;
    if (threadIdx.x == 0) {
        double lr = (double)Lre[p], li = (double)Lim[p];
        double dt = exp((double)log_step[p]);
        double mag = exp(lr * dt);
        double lam_r = mag * cos(li * dt);
        double lam_i = mag * sin(li * dt);
        d_Lam[p] = make_float2((float)lam_r, (float)lam_i);
        double nr = lam_r - 1.0, ni = lam_i;
        double den = lr * lr + li * li;
        s_f = make_float2((float)((nr * lr + ni * li) / den),
                          (float)((ni * lr - nr * li) / den));
        // lam^64 via 6 squarings (double)
        double pr = lam_r, pi = lam_i;
        #pragma unroll
        for (int i = 0; i < 6; i++) { double r2 = pr*pr - pi*pi, i2 = 2.0*pr*pi; pr = r2; pi = i2; }
        d_LamPow[p] = make_float2((float)pr, (float)pi);
    }
    __syncthreads();
    float fr = s_f.x, fi = s_f.y;
    for (int h = threadIdx.x; h < HH; h += blockDim.x) {
        float br = Bre[p * HH + h], bi = Bim[p * HH + h];
        d_W1[p * K1 + h]        = __float2half(fr * br - fi * bi);   // Re(B_bar)
        d_W1[(PP + p) * K1 + h] = __float2half(fr * bi + fi * br);   // Im(B_bar)
    }
}

__global__ void w2_kernel(const float* __restrict__ Cre, const float* __restrict__ Cim) {
    int idx = blockIdx.x * blockDim.x + threadIdx.x;
    int h = idx >> 9, p = idx & (PP - 1);
    d_W2[h * K2 + p]      = __float2half( 2.0f * Cre[h * PP + p]);
    d_W2[h * K2 + PP + p] = __float2half(-2.0f * Cim[h * PP + p]);
}

// vectorized: 8 floats -> 8 halves (one uint4 store) per thread
__global__ void uconv_kernel(const float* __restrict__ u) {
    size_t i = ((size_t)blockIdx.x * blockDim.x + threadIdx.x) * 8;
    float4 a = *(const float4*)(u + i);
    float4 b = *(const float4*)(u + i + 4);
    __half2 h0 = __floats2half2_rn(a.x, a.y);
    __half2 h1 = __floats2half2_rn(a.z, a.w);
    __half2 h2 = __floats2half2_rn(b.x, b.y);
    __half2 h3 = __floats2half2_rn(b.z, b.w);
    uint4 out;
    out.x = *(uint32_t*)&h0; out.y = *(uint32_t*)&h1;
    out.z = *(uint32_t*)&h2; out.w = *(uint32_t*)&h3;
    *(uint4*)(d_Uh + i) = out;
}

// ---------------- HMMA fp16 GEMM: C[m,n] = sum_k A[m,k]*W[n,k] ---------------
// 128x128 CTA tile, BK=64, 4 warps of 64x64 (128 threads).
// 3-stage cp.async pipeline, 128B-row XOR-swizzled tiles, 1 barrier/chunk.
#define TILE_B  (128 * 128)              // 16384 B
#define STAGE_B (2 * TILE_B)             // A, W = 32768 B
#define NSTAGE  3
#define GSMEM   (NSTAGE * STAGE_B)       // 98304 B

template <int OUT_HALF>
__global__ void __launch_bounds__(128, 2)
hmma_gemm(const __half* __restrict__ A, const __half* __restrict__ W,
          void* __restrict__ Cv, int N, int K) {
    extern __shared__ char smem[];
    const uint32_t sb = smem_u32(smem);
    const int tid = threadIdx.x;
    const int wid = tid >> 5, lane = tid & 31;
    const int wm = wid >> 1, wn = wid & 1;       // warp tile: rows wm*64, cols wn*64
    const int m0 = blockIdx.y * 128, n0 = blockIdx.x * 128;

    const char* srcs[2] = {
        (const char*)(A + (size_t)m0 * K),
        (const char*)(W + (size_t)n0 * K) };
    const size_t rstride = (size_t)K * 2;

    auto prefetch = [&](int stage, int ci) {
        #pragma unroll
        for (int it = 0; it < 16; it++) {
            int id = it * 128 + tid;            // 0..2047
            int t = id >> 10;                   // tile 0..1
            int w = id & 1023;
            int row = w >> 3, c = w & 7;
            cp16(sb + stage * STAGE_B + t * TILE_B + sw_off(row, c),
                 srcs[t] + (size_t)ci * 128 + (size_t)row * rstride + c * 16);
        }
    };

    float acc[4][8][4];
    #pragma unroll
    for (int i = 0; i < 4; i++)
        #pragma unroll
        for (int j = 0; j < 8; j++)
            #pragma unroll
            for (int q = 0; q < 4; q++) acc[i][j][q] = 0.f;

    const int nch = K / 64;
    prefetch(0, 0); CP_COMMIT();
    prefetch(1, 1); CP_COMMIT();

    // fragment address components (per lane)
    const int a_row = lane & 15;
    const int a_c   = lane >> 4;                  // +0 or +1 16B column
    const int b_row = (lane & 7) + ((lane >> 4) & 1) * 8;
    const int b_c   = (lane >> 3) & 1;

    int s = 0;
    for (int ci = 0; ci < nch; ci++) {
        CP_WAIT(1);
        __syncthreads();

        // prefetch into the stage freed at this barrier; overlaps MMA burst
        if (ci + 2 < nch) prefetch((s + 2) % NSTAGE, ci + 2);
        CP_COMMIT();

        uint32_t sA = sb + s * STAGE_B + 0 * TILE_B;
        uint32_t sW = sb + s * STAGE_B + 1 * TILE_B;

        #pragma unroll
        for (int ks = 0; ks < 4; ks++) {
            uint32_t bw[8][2], av[4][4];
            #pragma unroll
            for (int np = 0; np < 4; np++) {
                int brow = wn * 64 + np * 16 + b_row;
                uint32_t r[4];
                ldm_x4(sW + sw_off(brow, ks * 2 + b_c), r);
                bw[np*2][0] = r[0]; bw[np*2][1] = r[1];
                bw[np*2+1][0] = r[2]; bw[np*2+1][1] = r[3];
            }
            #pragma unroll
            for (int mt = 0; mt < 4; mt++) {
                int arow = wm * 64 + mt * 16 + a_row;
                ldm_x4(sA + sw_off(arow, ks * 2 + a_c), av[mt]);
            }
            #pragma unroll
            for (int mt = 0; mt < 4; mt++)
                #pragma unroll
                for (int nt = 0; nt < 8; nt++) hmma(acc[mt][nt], av[mt], bw[nt]);
        }
        s = (s + 1 == NSTAGE) ? 0 : s + 1;
    }

    // epilogue
    #pragma unroll
    for (int mt = 0; mt < 4; mt++) {
        int r = m0 + wm * 64 + mt * 16 + (lane >> 2);
        #pragma unroll
        for (int nt = 0; nt < 8; nt++) {
            int c = n0 + wn * 64 + nt * 8 + (lane & 3) * 2;
            if (OUT_HALF) {
                __half* C = (__half*)Cv;
                *(__half2*)(C + (size_t)r * N + c) =
                    __floats2half2_rn(acc[mt][nt][0], acc[mt][nt][1]);
                *(__half2*)(C + (size_t)(r + 8) * N + c) =
                    __floats2half2_rn(acc[mt][nt][2], acc[mt][nt][3]);
            } else {
                float* C = (float*)Cv;
                *(float2*)(C + (size_t)r * N + c)       = make_float2(acc[mt][nt][0], acc[mt][nt][1]);
                *(float2*)(C + (size_t)(r + 8) * N + c) = make_float2(acc[mt][nt][2], acc[mt][nt][3]);
            }
        }
    }
}

// ---------------- chunked complex scan over L (Bu fp16, 4 p's per thread) ----
__global__ void scan_phaseA() {
    int idx = blockIdx.x * blockDim.x + threadIdx.x;   // 0..65535
    int pv = idx & 127;                  // 4-half group; p0 = 4*pv
    int c  = (idx >> 7) & (NCHUNK - 1);
    int b  = idx >> 13;
    float2 lam[4];
    float xr[4], xi[4];
    #pragma unroll
    for (int q = 0; q < 4; q++) { lam[q] = d_Lam[4 * pv + q]; xr[q] = 0.f; xi[q] = 0.f; }
    size_t base = ((size_t)b * LL + (size_t)c * CLEN) * N1;
    const uint2* Xr = (const uint2*)(d_Bu + base) + pv;
    const uint2* Xi = (const uint2*)(d_Bu + base + PP) + pv;
    #pragma unroll 4
    for (int j = 0; j < CLEN; j++) {
        uint2 vr = Xr[(size_t)j * (N1 / 4)];
        uint2 vi = Xi[(size_t)j * (N1 / 4)];
        float2 br01 = __half22float2(*(__half2*)&vr.x);
        float2 br23 = __half22float2(*(__half2*)&vr.y);
        float2 bi01 = __half22float2(*(__half2*)&vi.x);
        float2 bi23 = __half22float2(*(__half2*)&vi.y);
        float br[4] = {br01.x, br01.y, br23.x, br23.y};
        float bi[4] = {bi01.x, bi01.y, bi23.x, bi23.y};
        #pragma unroll
        for (int q = 0; q < 4; q++) {
            float nr = fmaf(lam[q].x, xr[q], fmaf(-lam[q].y, xi[q], br[q]));
            float ni = fmaf(lam[q].x, xi[q], fmaf( lam[q].y, xr[q], bi[q]));
            xr[q] = nr; xi[q] = ni;
        }
    }
    int yb = (b * NCHUNK + c) * PP + 4 * pv;
    #pragma unroll
    for (int q = 0; q < 4; q++) d_yend[yb + q] = make_float2(xr[q], xi[q]);
}

__global__ void scan_phaseB() {
    int idx = blockIdx.x * blockDim.x + threadIdx.x;
    int p = idx & (PP - 1);
    int b = idx >> 9;
    float2 pw = d_LamPow[p];
    float cr = 0.f, ci = 0.f;
    #pragma unroll
    for (int c = 0; c < NCHUNK; c++) {
        d_cin[(b * NCHUNK + c) * PP + p] = make_float2(cr, ci);
        float2 ye = d_yend[(b * NCHUNK + c) * PP + p];
        float nr = fmaf(pw.x, cr, fmaf(-pw.y, ci, ye.x));
        float ni = fmaf(pw.x, ci, fmaf( pw.y, cr, ye.y));
        cr = nr; ci = ni;
    }
}

// phaseC: apply carry-in, emit xs rounded to fp16 for GEMM2
__global__ void scan_phaseC() {
    int idx = blockIdx.x * blockDim.x + threadIdx.x;
    int pv = idx & 127;
    int c  = (idx >> 7) & (NCHUNK - 1);
    int b  = idx >> 13;
    float2 lam[4];
    float xr[4], xi[4];
    int cb = (b * NCHUNK + c) * PP + 4 * pv;
    #pragma unroll
    for (int q = 0; q < 4; q++) {
        lam[q] = d_Lam[4 * pv + q];
        float2 c0 = d_cin[cb + q];
        xr[q] = c0.x; xi[q] = c0.y;
    }
    size_t mrow = (size_t)b * LL + (size_t)c * CLEN;
    const uint2* Xr = (const uint2*)(d_Bu + mrow * N1) + pv;
    const uint2* Xi = (const uint2*)(d_Bu + mrow * N1 + PP) + pv;
    uint2* Hr = (uint2*)(d_Xh + mrow * K2) + pv;
    uint2* Hi = (uint2*)(d_Xh + mrow * K2 + PP) + pv;
    #pragma unroll 4
    for (int j = 0; j < CLEN; j++) {
        uint2 vr = Xr[(size_t)j * (N1 / 4)];
        uint2 vi = Xi[(size_t)j * (N1 / 4)];
        float2 br01 = __half22float2(*(__half2*)&vr.x);
        float2 br23 = __half22float2(*(__half2*)&vr.y);
        float2 bi01 = __half22float2(*(__half2*)&vi.x);
        float2 bi23 = __half22float2(*(__half2*)&vi.y);
        float br[4] = {br01.x, br01.y, br23.x, br23.y};
        float bi[4] = {bi01.x, bi01.y, bi23.x, bi23.y};
        #pragma unroll
        for (int q = 0; q < 4; q++) {
            float nr = fmaf(lam[q].x, xr[q], fmaf(-lam[q].y, xi[q], br[q]));
            float ni = fmaf(lam[q].x, xi[q], fmaf( lam[q].y, xr[q], bi[q]));
            xr[q] = nr; xi[q] = ni;
        }
        __half2 hr01 = __floats2half2_rn(xr[0], xr[1]);
        __half2 hr23 = __floats2half2_rn(xr[2], xr[3]);
        __half2 hi01 = __floats2half2_rn(xi[0], xi[1]);
        __half2 hi23 = __floats2half2_rn(xi[2], xi[3]);
        uint2 wr, wi;
        wr.x = *(uint32_t*)&hr01; wr.y = *(uint32_t*)&hr23;
        wi.x = *(uint32_t*)&hi01; wi.y = *(uint32_t*)&hi23;
        Hr[(size_t)j * (K2 / 4)] = wr;
        Hi[(size_t)j * (K2 / 4)] = wi;
    }
}

// ---------------- launch -----------------------------------------------------
extern "C" void kernel_launch(void* const* d_in, const int* in_sizes, int n_in,
                              void* d_out, int out_size) {
    const float* Lre      = (const float*)d_in[0];
    const float* Lim      = (const float*)d_in[1];
    const float* Bre      = (const float*)d_in[2];
    const float* Bim      = (const float*)d_in[3];
    const float* Cre      = (const float*)d_in[4];
    const float* Cim      = (const float*)d_in[5];
    const float* log_step = (const float*)d_in[6];
    const float* u        = (const float*)d_in[7];
    float* out = (float*)d_out;

    __half *Bu, *Uh, *Xh, *W1p, *W2p;
    cudaGetSymbolAddress((void**)&Bu,  d_Bu);
    cudaGetSymbolAddress((void**)&Uh,  d_Uh);
    cudaGetSymbolAddress((void**)&Xh,  d_Xh);
    cudaGetSymbolAddress((void**)&W1p, d_W1);
    cudaGetSymbolAddress((void**)&W2p, d_W2);

    cudaFuncSetAttribute(hmma_gemm<1>, cudaFuncAttributeMaxDynamicSharedMemorySize, GSMEM);
    cudaFuncSetAttribute(hmma_gemm<0>, cudaFuncAttributeMaxDynamicSharedMemorySize, GSMEM);

    setup_kernel<<<PP, 256>>>(Lre, Lim, Bre, Bim, log_step);
    w2_kernel<<<(HH * PP) / 256, 256>>>(Cre, Cim);
    uconv_kernel<<<(int)(((size_t)MM * K1) / 8 / 256), 256>>>(u);

    // GEMM1: Bu(re|im) = u @ W1^T -> d_Bu fp16 (M x 1024)
    hmma_gemm<1><<<dim3(N1 / 128, MM / 128), 128, GSMEM>>>(Uh, W1p, Bu, N1, K1);

    // chunked complex scan; phaseC emits fp16 xs
    scan_phaseA<<<(BB * NCHUNK * PP / 4) / 256, 256>>>();
    scan_phaseB<<<(BB * PP) / 256, 256>>>();
    scan_phaseC<<<(BB * NCHUNK * PP / 4) / 256, 256>>>();

    // GEMM2: ys = xs @ W2^T -> out fp32 (M x 512)
    hmma_gemm<0><<<dim3(N2 / 128, MM / 128), 128, GSMEM>>>(Xh, W2p, out, N2, K2);
}

// round 13
// speedup vs baseline: 6.1514x; 1.0214x over previous
#include <cuda_runtime.h>
#include <cuda_fp16.h>
#include <math.h>
#include <stdint.h>

// Problem constants
#define BB    8
#define LL    4096
#define HH    512
#define PP    512
#define MM    (BB*LL)     // 32768 tokens
#define N1    (2*PP)      // 1024  (Bu_re | Bu_im)
#define K1    HH          // 512
#define N2    HH          // 512
#define K2    (2*PP)      // 1024  (x_re | x_im)
#define NCHUNK 64
#define CLEN   64         // LL / NCHUNK

// ---------------- static device scratch -------------------------------------
__device__ __half  d_Bu [(size_t)MM * N1];   // Bu fp16 (64MB)
__device__ __half  d_Uh [(size_t)MM * K1];   // u rounded to fp16 (32MB)
__device__ __half  d_Xh [(size_t)MM * K2];   // xs rounded to fp16 (64MB)
__device__ __half  d_W1 [N1 * K1];           // B_bar folded, fp16
__device__ __half  d_W2 [N2 * K2];           // [2C_re | -2C_im], fp16
__device__ float2 d_Lam[PP];
__device__ float2 d_LamPow[PP];              // lam^CLEN
__device__ float2 d_yend[BB * NCHUNK * PP];
__device__ float2 d_cin [BB * NCHUNK * PP];

// ---------------- helpers ----------------------------------------------------
__device__ __forceinline__ uint32_t smem_u32(const void* p) {
    uint32_t a;
    asm("{ .reg .u64 t; cvta.to.shared.u64 t, %1; cvt.u32.u64 %0, t; }" : "=r"(a) : "l"(p));
    return a;
}
__device__ __forceinline__ void cp16(uint32_t saddr, const void* g) {
    asm volatile("cp.async.cg.shared.global [%0], [%1], 16;" :: "r"(saddr), "l"(g));
}
#define CP_COMMIT() asm volatile("cp.async.commit_group;" ::: "memory")
#define CP_WAIT(n)  asm volatile("cp.async.wait_group %0;" :: "n"(n) : "memory")

__device__ __forceinline__ void ldm_x4(uint32_t addr, uint32_t* r) {
    asm volatile("ldmatrix.sync.aligned.m8n8.x4.shared.b16 {%0,%1,%2,%3}, [%4];"
                 : "=r"(r[0]), "=r"(r[1]), "=r"(r[2]), "=r"(r[3]) : "r"(addr));
}
__device__ __forceinline__ void hmma(float* c, const uint32_t* a, const uint32_t* b) {
    asm volatile(
        "mma.sync.aligned.m16n8k16.row.col.f32.f16.f16.f32 "
        "{%0,%1,%2,%3}, {%4,%5,%6,%7}, {%8,%9}, {%0,%1,%2,%3};"
        : "+f"(c[0]), "+f"(c[1]), "+f"(c[2]), "+f"(c[3])
        : "r"(a[0]), "r"(a[1]), "r"(a[2]), "r"(a[3]), "r"(b[0]), "r"(b[1]));
}

// XOR swizzle inside a 128-row x 64B tile: (row, c16 in 0..3) -> byte offset
__device__ __forceinline__ uint32_t sw_off(int row, int c16) {
    return (uint32_t)(row * 64 + ((c16 ^ ((row >> 1) & 3)) << 4));
}

// ---------------- setup: discretize in fp64, build W1 ------------------------
__global__ void setup_kernel(const float* __restrict__ Lre, const float* __restrict__ Lim,
                             const float* __restrict__ Bre, const float* __restrict__ Bim,
                             const float* __restrict__ log_step) {
    int p = blockIdx.x;
    __shared__ float2 s_f;
    if (threadIdx.x == 0) {
        double lr = (double)Lre[p], li = (double)Lim[p];
        double dt = exp((double)log_step[p]);
        double mag = exp(lr * dt);
        double lam_r = mag * cos(li * dt);
        double lam_i = mag * sin(li * dt);
        d_Lam[p] = make_float2((float)lam_r, (float)lam_i);
        double nr = lam_r - 1.0, ni = lam_i;
        double den = lr * lr + li * li;
        s_f = make_float2((float)((nr * lr + ni * li) / den),
                          (float)((ni * lr - nr * li) / den));
        // lam^64 via 6 squarings (double)
        double pr = lam_r, pi = lam_i;
        #pragma unroll
        for (int i = 0; i < 6; i++) { double r2 = pr*pr - pi*pi, i2 = 2.0*pr*pi; pr = r2; pi = i2; }
        d_LamPow[p] = make_float2((float)pr, (float)pi);
    }
    __syncthreads();
    float fr = s_f.x, fi = s_f.y;
    for (int h = threadIdx.x; h < HH; h += blockDim.x) {
        float br = Bre[p * HH + h], bi = Bim[p * HH + h];
        d_W1[p * K1 + h]        = __float2half(fr * br - fi * bi);   // Re(B_bar)
        d_W1[(PP + p) * K1 + h] = __float2half(fr * bi + fi * br);   // Im(B_bar)
    }
}

__global__ void w2_kernel(const float* __restrict__ Cre, const float* __restrict__ Cim) {
    int idx = blockIdx.x * blockDim.x + threadIdx.x;
    int h = idx >> 9, p = idx & (PP - 1);
    d_W2[h * K2 + p]      = __float2half( 2.0f * Cre[h * PP + p]);
    d_W2[h * K2 + PP + p] = __float2half(-2.0f * Cim[h * PP + p]);
}

// vectorized: 8 floats -> 8 halves (one uint4 store) per thread
__global__ void uconv_kernel(const float* __restrict__ u) {
    size_t i = ((size_t)blockIdx.x * blockDim.x + threadIdx.x) * 8;
    float4 a = *(const float4*)(u + i);
    float4 b = *(const float4*)(u + i + 4);
    __half2 h0 = __floats2half2_rn(a.x, a.y);
    __half2 h1 = __floats2half2_rn(a.z, a.w);
    __half2 h2 = __floats2half2_rn(b.x, b.y);
    __half2 h3 = __floats2half2_rn(b.z, b.w);
    uint4 out;
    out.x = *(uint32_t*)&h0; out.y = *(uint32_t*)&h1;
    out.z = *(uint32_t*)&h2; out.w = *(uint32_t*)&h3;
    *(uint4*)(d_Uh + i) = out;
}

// ---------------- HMMA fp16 GEMM: C[m,n] = sum_k A[m,k]*W[n,k] ---------------
// 128x128 CTA tile, BK=32, 4 warps of 64x64 (128 threads).
// 4-stage cp.async pipeline, 64B-row XOR-swizzled tiles, 1 barrier/chunk.
// A-fragment lookahead: ldmatrix of mt+1 issued before mt's HMMA burst.
#define TILE_B  (128 * 64)               // 8192 B
#define STAGE_B (2 * TILE_B)             // A, W = 16384 B
#define NSTAGE  4
#define GSMEM   (NSTAGE * STAGE_B)       // 65536 B

template <int OUT_HALF>
__global__ void __launch_bounds__(128, 2)
hmma_gemm(const __half* __restrict__ A, const __half* __restrict__ W,
          void* __restrict__ Cv, int N, int K) {
    extern __shared__ char smem[];
    const uint32_t sb = smem_u32(smem);
    const int tid = threadIdx.x;
    const int wid = tid >> 5, lane = tid & 31;
    const int wm = wid >> 1, wn = wid & 1;       // warp tile: rows wm*64, cols wn*64
    const int m0 = blockIdx.y * 128, n0 = blockIdx.x * 128;

    const char* srcs[2] = {
        (const char*)(A + (size_t)m0 * K),
        (const char*)(W + (size_t)n0 * K) };
    const size_t rstride = (size_t)K * 2;

    auto prefetch = [&](int stage, int ci) {
        #pragma unroll
        for (int it = 0; it < 8; it++) {
            int id = it * 128 + tid;            // 0..1023
            int t = id >> 9;                    // tile 0..1
            int w = id & 511;
            int row = w >> 2, c = w & 3;
            cp16(sb + stage * STAGE_B + t * TILE_B + sw_off(row, c),
                 srcs[t] + (size_t)ci * 64 + (size_t)row * rstride + c * 16);
        }
    };

    float acc[4][8][4];
    #pragma unroll
    for (int i = 0; i < 4; i++)
        #pragma unroll
        for (int j = 0; j < 8; j++)
            #pragma unroll
            for (int q = 0; q < 4; q++) acc[i][j][q] = 0.f;

    const int nch = K / 32;
    prefetch(0, 0); CP_COMMIT();
    prefetch(1, 1); CP_COMMIT();
    prefetch(2, 2); CP_COMMIT();

    // fragment address components (per lane)
    const int a_row = lane & 15;
    const int a_c   = lane >> 4;                  // +0 or +1 16B column
    const int b_row = (lane & 7) + ((lane >> 4) & 1) * 8;
    const int b_c   = (lane >> 3) & 1;

    int s = 0;
    for (int ci = 0; ci < nch; ci++) {
        CP_WAIT(2);
        __syncthreads();

        uint32_t sA = sb + s * STAGE_B + 0 * TILE_B;
        uint32_t sW = sb + s * STAGE_B + 1 * TILE_B;

        #pragma unroll
        for (int ks = 0; ks < 2; ks++) {
            // B fragments up front
            uint32_t bw[8][2];
            #pragma unroll
            for (int np = 0; np < 4; np++) {
                int brow = wn * 64 + np * 16 + b_row;
                uint32_t r[4];
                ldm_x4(sW + sw_off(brow, ks * 2 + b_c), r);
                bw[np*2][0] = r[0]; bw[np*2][1] = r[1];
                bw[np*2+1][0] = r[2]; bw[np*2+1][1] = r[3];
            }
            // A-fragment lookahead: double-buffered in registers
            uint32_t av[2][4];
            ldm_x4(sA + sw_off(wm * 64 + a_row, ks * 2 + a_c), av[0]);
            #pragma unroll
            for (int mt = 0; mt < 4; mt++) {
                if (mt < 3) {
                    int arow = wm * 64 + (mt + 1) * 16 + a_row;
                    ldm_x4(sA + sw_off(arow, ks * 2 + a_c), av[(mt + 1) & 1]);
                }
                #pragma unroll
                for (int nt = 0; nt < 8; nt++) hmma(acc[mt][nt], av[mt & 1], bw[nt]);
            }
        }
        // prefetch 3 chunks ahead into the stage freed by this iteration
        if (ci + 3 < nch) prefetch((s + 3) & 3, ci + 3);
        CP_COMMIT();
        s = (s + 1) & 3;
    }

    // epilogue
    #pragma unroll
    for (int mt = 0; mt < 4; mt++) {
        int r = m0 + wm * 64 + mt * 16 + (lane >> 2);
        #pragma unroll
        for (int nt = 0; nt < 8; nt++) {
            int c = n0 + wn * 64 + nt * 8 + (lane & 3) * 2;
            if (OUT_HALF) {
                __half* C = (__half*)Cv;
                *(__half2*)(C + (size_t)r * N + c) =
                    __floats2half2_rn(acc[mt][nt][0], acc[mt][nt][1]);
                *(__half2*)(C + (size_t)(r + 8) * N + c) =
                    __floats2half2_rn(acc[mt][nt][2], acc[mt][nt][3]);
            } else {
                float* C = (float*)Cv;
                *(float2*)(C + (size_t)r * N + c)       = make_float2(acc[mt][nt][0], acc[mt][nt][1]);
                *(float2*)(C + (size_t)(r + 8) * N + c) = make_float2(acc[mt][nt][2], acc[mt][nt][3]);
            }
        }
    }
}

// ---------------- chunked complex scan over L (Bu fp16, 4 p's per thread) ----
__global__ void scan_phaseA() {
    int idx = blockIdx.x * blockDim.x + threadIdx.x;
    int pv = idx & 127;                  // 4-half group; p0 = 4*pv
    int c  = (idx >> 7) & (NCHUNK - 1);
    int b  = idx >> 13;
    float2 lam[4];
    float xr[4], xi[4];
    #pragma unroll
    for (int q = 0; q < 4; q++) { lam[q] = d_Lam[4 * pv + q]; xr[q] = 0.f; xi[q] = 0.f; }
    size_t base = ((size_t)b * LL + (size_t)c * CLEN) * N1;
    const uint2* Xr = (const uint2*)(d_Bu + base) + pv;
    const uint2* Xi = (const uint2*)(d_Bu + base + PP) + pv;
    #pragma unroll 4
    for (int j = 0; j < CLEN; j++) {
        uint2 vr = Xr[(size_t)j * (N1 / 4)];
        uint2 vi = Xi[(size_t)j * (N1 / 4)];
        float2 br01 = __half22float2(*(__half2*)&vr.x);
        float2 br23 = __half22float2(*(__half2*)&vr.y);
        float2 bi01 = __half22float2(*(__half2*)&vi.x);
        float2 bi23 = __half22float2(*(__half2*)&vi.y);
        float br[4] = {br01.x, br01.y, br23.x, br23.y};
        float bi[4] = {bi01.x, bi01.y, bi23.x, bi23.y};
        #pragma unroll
        for (int q = 0; q < 4; q++) {
            float nr = fmaf(lam[q].x, xr[q], fmaf(-lam[q].y, xi[q], br[q]));
            float ni = fmaf(lam[q].x, xi[q], fmaf( lam[q].y, xr[q], bi[q]));
            xr[q] = nr; xi[q] = ni;
        }
    }
    int yb = (b * NCHUNK + c) * PP + 4 * pv;
    #pragma unroll
    for (int q = 0; q < 4; q++) d_yend[yb + q] = make_float2(xr[q], xi[q]);
}

__global__ void scan_phaseB() {
    int idx = blockIdx.x * blockDim.x + threadIdx.x;
    int p = idx & (PP - 1);
    int b = idx >> 9;
    float2 pw = d_LamPow[p];
    float cr = 0.f, ci = 0.f;
    #pragma unroll
    for (int c = 0; c < NCHUNK; c++) {
        d_cin[(b * NCHUNK + c) * PP + p] = make_float2(cr, ci);
        float2 ye = d_yend[(b * NCHUNK + c) * PP + p];
        float nr = fmaf(pw.x, cr, fmaf(-pw.y, ci, ye.x));
        float ni = fmaf(pw.x, ci, fmaf( pw.y, cr, ye.y));
        cr = nr; ci = ni;
    }
}

// phaseC: apply carry-in, emit xs rounded to fp16 for GEMM2
__global__ void scan_phaseC() {
    int idx = blockIdx.x * blockDim.x + threadIdx.x;
    int pv = idx & 127;
    int c  = (idx >> 7) & (NCHUNK - 1);
    int b  = idx >> 13;
    float2 lam[4];
    float xr[4], xi[4];
    int cb = (b * NCHUNK + c) * PP + 4 * pv;
    #pragma unroll
    for (int q = 0; q < 4; q++) {
        lam[q] = d_Lam[4 * pv + q];
        float2 c0 = d_cin[cb + q];
        xr[q] = c0.x; xi[q] = c0.y;
    }
    size_t mrow = (size_t)b * LL + (size_t)c * CLEN;
    const uint2* Xr = (const uint2*)(d_Bu + mrow * N1) + pv;
    const uint2* Xi = (const uint2*)(d_Bu + mrow * N1 + PP) + pv;
    uint2* Hr = (uint2*)(d_Xh + mrow * K2) + pv;
    uint2* Hi = (uint2*)(d_Xh + mrow * K2 + PP) + pv;
    #pragma unroll 4
    for (int j = 0; j < CLEN; j++) {
        uint2 vr = Xr[(size_t)j * (N1 / 4)];
        uint2 vi = Xi[(size_t)j * (N1 / 4)];
        float2 br01 = __half22float2(*(__half2*)&vr.x);
        float2 br23 = __half22float2(*(__half2*)&vr.y);
        float2 bi01 = __half22float2(*(__half2*)&vi.x);
        float2 bi23 = __half22float2(*(__half2*)&vi.y);
        float br[4] = {br01.x, br01.y, br23.x, br23.y};
        float bi[4] = {bi01.x, bi01.y, bi23.x, bi23.y};
        #pragma unroll
        for (int q = 0; q < 4; q++) {
            float nr = fmaf(lam[q].x, xr[q], fmaf(-lam[q].y, xi[q], br[q]));
            float ni = fmaf(lam[q].x, xi[q], fmaf( lam[q].y, xr[q], bi[q]));
            xr[q] = nr; xi[q] = ni;
        }
        __half2 hr01 = __floats2half2_rn(xr[0], xr[1]);
        __half2 hr23 = __floats2half2_rn(xr[2], xr[3]);
        __half2 hi01 = __floats2half2_rn(xi[0], xi[1]);
        __half2 hi23 = __floats2half2_rn(xi[2], xi[3]);
        uint2 wr, wi;
        wr.x = *(uint32_t*)&hr01; wr.y = *(uint32_t*)&hr23;
        wi.x = *(uint32_t*)&hi01; wi.y = *(uint32_t*)&hi23;
        Hr[(size_t)j * (K2 / 4)] = wr;
        Hi[(size_t)j * (K2 / 4)] = wi;
    }
}

// ---------------- launch -----------------------------------------------------
extern "C" void kernel_launch(void* const* d_in, const int* in_sizes, int n_in,
                              void* d_out, int out_size) {
    const float* Lre      = (const float*)d_in[0];
    const float* Lim      = (const float*)d_in[1];
    const float* Bre      = (const float*)d_in[2];
    const float* Bim      = (const float*)d_in[3];
    const float* Cre      = (const float*)d_in[4];
    const float* Cim      = (const float*)d_in[5];
    const float* log_step = (const float*)d_in[6];
    const float* u        = (const float*)d_in[7];
    float* out = (float*)d_out;

    __half *Bu, *Uh, *Xh, *W1p, *W2p;
    cudaGetSymbolAddress((void**)&Bu,  d_Bu);
    cudaGetSymbolAddress((void**)&Uh,  d_Uh);
    cudaGetSymbolAddress((void**)&Xh,  d_Xh);
    cudaGetSymbolAddress((void**)&W1p, d_W1);
    cudaGetSymbolAddress((void**)&W2p, d_W2);

    cudaFuncSetAttribute(hmma_gemm<1>, cudaFuncAttributeMaxDynamicSharedMemorySize, GSMEM);
    cudaFuncSetAttribute(hmma_gemm<0>, cudaFuncAttributeMaxDynamicSharedMemorySize, GSMEM);

    setup_kernel<<<PP, 256>>>(Lre, Lim, Bre, Bim, log_step);
    w2_kernel<<<(HH * PP) / 256, 256>>>(Cre, Cim);
    uconv_kernel<<<(int)(((size_t)MM * K1) / 8 / 256), 256>>>(u);

    // GEMM1: Bu(re|im) = u @ W1^T -> d_Bu fp16 (M x 1024)
    hmma_gemm<1><<<dim3(N1 / 128, MM / 128), 128, GSMEM>>>(Uh, W1p, Bu, N1, K1);

    // chunked complex scan; phaseC emits fp16 xs
    scan_phaseA<<<(BB * NCHUNK * PP / 4) / 256, 256>>>();
    scan_phaseB<<<(BB * PP) / 256, 256>>>();
    scan_phaseC<<<(BB * NCHUNK * PP / 4) / 256, 256>>>();

    // GEMM2: ys = xs @ W2^T -> out fp32 (M x 512)
    hmma_gemm<0><<<dim3(N2 / 128, MM / 128), 128, GSMEM>>>(Xh, W2p, out, N2, K2);
}